// round 10
// baseline (speedup 1.0000x reference)
#include <cuda_runtime.h>
#include <cuda_bf16.h>
#include <cstdint>

// ======================= constants =======================
#define NH      16
#define NQ      4096
#define NKV     8192
#define HD      128
#define PREFIX  (NKV - NQ)
#define BQ      128
#define BK      64
#define THREADS 256
#define LOG2E   1.4426950408889634f
#define SOFT_C  10.0f

#define KVELEMS (NH * NKV * HD)        // 16,777,216 per tensor

// bf16 tiles: 64 rows x 128 elems, row stride 272B (+16B pad, ldsm conflict-free)
#define KROW    272
#define KTILE   17408                  // 64*272
// smem layout (bytes), all double buffered
#define KB(b)   ((b) * 34816)          // K hi+lo          [0, 69632)
#define VB(b)   (69632 + (b) * 34816)  // V hi+lo          [69632, 139264)
#define MSB(b)  (139264 + (b) * 32768) // mask f32         [139264, 204800)
#define SMEM_BYTES 204800
// Q staging scratch (prologue only; disjoint from tile-0 targets KB(0)/VB(0)/MSB(0))
#define QSH     VB(1)
#define QSL     KB(1)

// ======================= persistent bf16 hi/lo copies of K and V =======================
__device__ __align__(16) __nv_bfloat16 g_kh[KVELEMS];
__device__ __align__(16) __nv_bfloat16 g_kl[KVELEMS];
__device__ __align__(16) __nv_bfloat16 g_vh[KVELEMS];
__device__ __align__(16) __nv_bfloat16 g_vl[KVELEMS];

// ======================= PTX helpers (base ISA only) =======================
__device__ __forceinline__ uint32_t smem_to_u32(const void* p) {
    uint32_t a;
    asm("{ .reg .u64 t; cvta.to.shared.u64 t, %1; cvt.u32.u64 %0, t; }" : "=r"(a) : "l"(p));
    return a;
}
__device__ __forceinline__ void ldsm_x4(uint32_t addr, uint32_t* r) {
    asm volatile("ldmatrix.sync.aligned.m8n8.x4.shared.b16 {%0,%1,%2,%3}, [%4];"
                 : "=r"(r[0]), "=r"(r[1]), "=r"(r[2]), "=r"(r[3]) : "r"(addr));
}
__device__ __forceinline__ void ldsm_x4_t(uint32_t addr, uint32_t* r) {
    asm volatile("ldmatrix.sync.aligned.m8n8.x4.trans.shared.b16 {%0,%1,%2,%3}, [%4];"
                 : "=r"(r[0]), "=r"(r[1]), "=r"(r[2]), "=r"(r[3]) : "r"(addr));
}
__device__ __forceinline__ void mma_bf16(float* c, const uint32_t* a, uint32_t b0, uint32_t b1) {
    asm volatile("mma.sync.aligned.m16n8k16.row.col.f32.bf16.bf16.f32 "
                 "{%0,%1,%2,%3}, {%4,%5,%6,%7}, {%8,%9}, {%0,%1,%2,%3};"
                 : "+f"(c[0]), "+f"(c[1]), "+f"(c[2]), "+f"(c[3])
                 : "r"(a[0]), "r"(a[1]), "r"(a[2]), "r"(a[3]), "r"(b0), "r"(b1));
}
__device__ __forceinline__ uint32_t packbf(float lo, float hi) {
    uint32_t r;
    asm("cvt.rn.bf16x2.f32 %0, %1, %2;" : "=r"(r) : "f"(hi), "f"(lo));
    return r;
}
__device__ __forceinline__ float ex2f(float x) {
    float r; asm("ex2.approx.f32 %0, %1;" : "=f"(r) : "f"(x)); return r;
}
__device__ __forceinline__ void split2(float a, float b, uint32_t& hi, uint32_t& lo) {
    hi = packbf(a, b);
    float fa = __uint_as_float(hi << 16);
    float fb = __uint_as_float(hi & 0xffff0000u);
    lo = packbf(a - fa, b - fb);
}
__device__ __forceinline__ void cp_async16(uint32_t dst, const void* src) {
    asm volatile("cp.async.cg.shared.global [%0], [%1], 16;" :: "r"(dst), "l"(src) : "memory");
}
#define CP_COMMIT() asm volatile("cp.async.commit_group;" ::: "memory")
#define CP_WAIT(n)  asm volatile("cp.async.wait_group %0;" :: "n"(n) : "memory")

// ======================= prep kernel: K/V f32 -> bf16 hi/lo =======================
__global__ void __launch_bounds__(256)
prep_kernel(const float* __restrict__ K, const float* __restrict__ V)
{
    const size_t n4 = KVELEMS / 4;
    size_t i = (size_t)blockIdx.x * 256 + threadIdx.x;   // one float4 per thread
    const float* src;
    __nv_bfloat16 *dh, *dl;
    size_t j;
    if (i < n4) { src = K; dh = g_kh; dl = g_kl; j = i; }
    else        { src = V; dh = g_vh; dl = g_vl; j = i - n4; }
    float4 v = ((const float4*)src)[j];
    uint32_t h01, l01, h23, l23;
    split2(v.x, v.y, h01, l01);
    split2(v.z, v.w, h23, l23);
    ((uint2*)dh)[j] = make_uint2(h01, h23);
    ((uint2*)dl)[j] = make_uint2(l01, l23);
}

// prefetch one 64x128 bf16 tile (256B rows) into padded smem (272B rows)
__device__ __forceinline__ void fetch_bf16_tile(uint32_t smdst, const __nv_bfloat16* gsrc, int tid) {
#pragma unroll
    for (int i = 0; i < 4; i++) {
        int gi  = tid + i * THREADS;       // 0..1023
        int row = gi >> 4, c = gi & 15;    // 16B chunks per 256B row
        cp_async16(smdst + row * KROW + c * 16, gsrc + (size_t)row * HD + c * 8);
    }
}

// ======================= main kernel =======================
__global__ void __launch_bounds__(THREADS, 1)
fsdpa_mma(const float* __restrict__ Qg, const float* __restrict__ Mg,
          float* __restrict__ Og)
{
    extern __shared__ char smem[];
    const uint32_t smb = smem_to_u32(smem);
    const int tid  = threadIdx.x;
    const int lane = tid & 31;
    const int wid  = tid >> 5;
    const int g    = lane >> 2;
    const int t2   = lane & 3;
    const int h    = blockIdx.y;
    const int q0   = (int)(gridDim.x - 1 - blockIdx.x) * BQ;  // longest work first
    const int wq   = wid * 16;
    // SMSP pair = {wid, wid+4}; stagger their loop phase by half a loop
    const int soff = ((wid >> 2) & 1) * 8;

    const size_t kvbase = (size_t)h * NKV * HD;
    const int ntiles = (PREFIX + q0 + BQ) / BK;

    // ---- prefetch tile 0 (K,V bf16 hi/lo + mask) into buffer 0 ----
    fetch_bf16_tile(smb + KB(0),         g_kh + kvbase, tid);
    fetch_bf16_tile(smb + KB(0) + KTILE, g_kl + kvbase, tid);
    fetch_bf16_tile(smb + VB(0),         g_vh + kvbase, tid);
    fetch_bf16_tile(smb + VB(0) + KTILE, g_vl + kvbase, tid);
#pragma unroll
    for (int i = 0; i < 8; i++) {
        int gi = tid + i * THREADS;
        int row = gi >> 4, c4 = gi & 15;
        cp_async16(smb + MSB(0) + row * 256 + c4 * 16, Mg + (size_t)(q0 + row) * NKV + c4 * 4);
    }
    CP_COMMIT();

    // ---- stage Q (scale folded) into scratch (buffer-1 regions), ldmatrix to regs ----
    {
        const float scale = 0.08838834764831845f;   // 1/sqrt(128)
        const float* qb = Qg + ((size_t)h * NQ + q0) * HD;
#pragma unroll
        for (int i = 0; i < 16; i++) {
            int gi  = tid + i * THREADS;
            int row = gi >> 5, c4 = (gi & 31) << 2;
            float4 v = *(const float4*)(qb + (size_t)row * HD + c4);
            v.x *= scale; v.y *= scale; v.z *= scale; v.w *= scale;
            uint32_t h01, l01, h23, l23;
            split2(v.x, v.y, h01, l01);
            split2(v.z, v.w, h23, l23);
            int off = row * KROW + c4 * 2;
            *(uint2*)(smem + QSH + off) = make_uint2(h01, h23);
            *(uint2*)(smem + QSL + off) = make_uint2(l01, l23);
        }
    }
    __syncthreads();

    uint32_t qh[8][4], ql[8][4];
    {
        const int mi = lane >> 3;
        const uint32_t ro = (uint32_t)(wq + (lane & 7) + ((mi & 1) << 3)) * KROW + ((mi >> 1) << 4);
#pragma unroll
        for (int kc = 0; kc < 8; kc++) {
            ldsm_x4(smb + QSH + ro + kc * 32, qh[kc]);
            ldsm_x4(smb + QSL + ro + kc * 32, ql[kc]);
        }
    }
    // buffer-1 regions freed after loop-top __syncthreads (t=0)

    float o[16][4];
#pragma unroll
    for (int i = 0; i < 16; i++)
#pragma unroll
        for (int j = 0; j < 4; j++) o[i][j] = 0.0f;
    float ls0 = 0.0f, ls1 = 0.0f;

    const float zb = -SOFT_C * LOG2E;

    for (int t = 0; t < ntiles; t++) {
        const int kv0 = t * BK;
        const int buf = t & 1;
        const int kbh = KB(buf), kbl = kbh + KTILE;
        const int vbh = VB(buf), vbl = vbh + KTILE;
        const float* msf = (const float*)(smem + MSB(buf));

        // tile t data arrived; all warps done with buffer buf^1 (previous tile)
        CP_WAIT(0);
        __syncthreads();

        // prefetch tile t+1 into buffer buf^1
        if (t + 1 < ntiles) {
            const size_t nb = kvbase + (size_t)(kv0 + BK) * HD;
            fetch_bf16_tile(smb + KB(buf ^ 1),         g_kh + nb, tid);
            fetch_bf16_tile(smb + KB(buf ^ 1) + KTILE, g_kl + nb, tid);
            fetch_bf16_tile(smb + VB(buf ^ 1),         g_vh + nb, tid);
            fetch_bf16_tile(smb + VB(buf ^ 1) + KTILE, g_vl + nb, tid);
#pragma unroll
            for (int i = 0; i < 8; i++) {
                int gi = tid + i * THREADS;
                int row = gi >> 4, c4 = gi & 15;
                cp_async16(smb + MSB(buf ^ 1) + row * 256 + c4 * 16,
                           Mg + (size_t)(q0 + row) * NKV + (kv0 + BK) + c4 * 4);
            }
        }
        CP_COMMIT();

        // ---- S = Q @ K^T: 16 steps, SMSP-pair phase-staggered ----
        float s[8][4];
#pragma unroll
        for (int i = 0; i < 8; i++)
#pragma unroll
            for (int j = 0; j < 4; j++) s[i][j] = 0.0f;

#pragma unroll
        for (int ii = 0; ii < 16; ii++) {
            const int i   = (ii + soff) & 15;
            const int kcp = i >> 2, ntg = i & 3;
            const int kc  = 2 * kcp;
            const int nt0 = 2 * ntg, nt1 = nt0 + 1;
            const uint32_t rb0 = (uint32_t)(nt0 * 8 + (lane & 7)) * KROW
                               + ((lane >> 3) << 4) + kcp * 64;
            const uint32_t rb1 = rb0 + 8 * KROW;
            uint32_t h0[4], l0[4], h1[4], l1[4];
            ldsm_x4(smb + kbh + rb0, h0);
            ldsm_x4(smb + kbl + rb0, l0);
            ldsm_x4(smb + kbh + rb1, h1);
            ldsm_x4(smb + kbl + rb1, l1);
            mma_bf16(s[nt0], qh[kc],     h0[0], h0[1]);
            mma_bf16(s[nt1], qh[kc],     h1[0], h1[1]);
            mma_bf16(s[nt0], qh[kc],     l0[0], l0[1]);
            mma_bf16(s[nt1], qh[kc],     l1[0], l1[1]);
            mma_bf16(s[nt0], ql[kc],     h0[0], h0[1]);
            mma_bf16(s[nt1], ql[kc],     h1[0], h1[1]);
            mma_bf16(s[nt0], qh[kc + 1], h0[2], h0[3]);
            mma_bf16(s[nt1], qh[kc + 1], h1[2], h1[3]);
            mma_bf16(s[nt0], qh[kc + 1], l0[2], l0[3]);
            mma_bf16(s[nt1], qh[kc + 1], l1[2], l1[3]);
            mma_bf16(s[nt0], ql[kc + 1], h0[2], h0[3]);
            mma_bf16(s[nt1], ql[kc + 1], h1[2], h1[3]);
        }

        // ---- softmax (fixed shift) ----
        {
            const int  lim0 = PREFIX + q0 + wq + g - kv0;
            const int  lim1 = lim0 + 8;
            const bool dg   = (t >= ntiles - 2);
            const float* mrow0 = msf + (wq + g) * 64;
            const float* mrow1 = mrow0 + 8 * 64;
#pragma unroll
            for (int nt = 0; nt < 8; nt++) {
                const int c = nt * 8 + t2 * 2;
                float2 m0 = *(const float2*)(mrow0 + c);
                float2 m1 = *(const float2*)(mrow1 + c);
                float z00 = fmaf(s[nt][0] + m0.x, LOG2E, zb);
                float z01 = fmaf(s[nt][1] + m0.y, LOG2E, zb);
                float z10 = fmaf(s[nt][2] + m1.x, LOG2E, zb);
                float z11 = fmaf(s[nt][3] + m1.y, LOG2E, zb);
                if (dg) {
                    if (c     > lim0) z00 = -127.0f;
                    if (c + 1 > lim0) z01 = -127.0f;
                    if (c     > lim1) z10 = -127.0f;
                    if (c + 1 > lim1) z11 = -127.0f;
                }
                float p00 = ex2f(z00), p01 = ex2f(z01);
                float p10 = ex2f(z10), p11 = ex2f(z11);
                ls0 += p00 + p01;
                ls1 += p10 + p11;
                s[nt][0] = p00; s[nt][1] = p01; s[nt][2] = p10; s[nt][3] = p11;
            }
        }

        // ---- O += P @ V: 16 steps, SMSP-pair phase-staggered ----
        {
            uint32_t ah[4], al[4];
#pragma unroll
            for (int ii = 0; ii < 16; ii++) {
                const int i  = (ii + soff) & 15;
                const int kc = i >> 2, pg = i & 3;
                if ((ii & 3) == 0) {   // soff is a multiple of 4 -> pg==0 exactly here
                    split2(s[2 * kc][0],     s[2 * kc][1],     ah[0], al[0]);
                    split2(s[2 * kc][2],     s[2 * kc][3],     ah[1], al[1]);
                    split2(s[2 * kc + 1][0], s[2 * kc + 1][1], ah[2], al[2]);
                    split2(s[2 * kc + 1][2], s[2 * kc + 1][3], ah[3], al[3]);
                }
                const uint32_t rv = (uint32_t)(kc * 16 + ((lane >> 3) & 1) * 8 + (lane & 7)) * KROW
                                  + ((lane >> 4) << 4);
                const int p0 = 2 * pg, p1 = p0 + 1;
                uint32_t vh0[4], vl0[4], vh1[4], vl1[4];
                ldsm_x4_t(smb + vbh + rv + p0 * 32, vh0);
                ldsm_x4_t(smb + vbl + rv + p0 * 32, vl0);
                ldsm_x4_t(smb + vbh + rv + p1 * 32, vh1);
                ldsm_x4_t(smb + vbl + rv + p1 * 32, vl1);
                mma_bf16(o[2 * p0],     ah, vh0[0], vh0[1]);
                mma_bf16(o[2 * p0 + 1], ah, vh0[2], vh0[3]);
                mma_bf16(o[2 * p1],     ah, vh1[0], vh1[1]);
                mma_bf16(o[2 * p1 + 1], ah, vh1[2], vh1[3]);
                mma_bf16(o[2 * p0],     ah, vl0[0], vl0[1]);
                mma_bf16(o[2 * p0 + 1], ah, vl0[2], vl0[3]);
                mma_bf16(o[2 * p1],     ah, vl1[0], vl1[1]);
                mma_bf16(o[2 * p1 + 1], ah, vl1[2], vl1[3]);
                mma_bf16(o[2 * p0],     al, vh0[0], vh0[1]);
                mma_bf16(o[2 * p0 + 1], al, vh0[2], vh0[3]);
                mma_bf16(o[2 * p1],     al, vh1[0], vh1[1]);
                mma_bf16(o[2 * p1 + 1], al, vh1[2], vh1[3]);
            }
        }
    }

    // ---- epilogue ----
    ls0 += __shfl_xor_sync(0xffffffffu, ls0, 1);
    ls0 += __shfl_xor_sync(0xffffffffu, ls0, 2);
    ls1 += __shfl_xor_sync(0xffffffffu, ls1, 1);
    ls1 += __shfl_xor_sync(0xffffffffu, ls1, 2);
    const float i0 = 1.0f / ls0;
    const float i1 = 1.0f / ls1;

    float* ob = Og + ((size_t)h * NQ + q0 + wq) * HD;
#pragma unroll
    for (int nt = 0; nt < 16; nt++) {
        const int c = nt * 8 + t2 * 2;
        float2 w0 = make_float2(o[nt][0] * i0, o[nt][1] * i0);
        float2 w1 = make_float2(o[nt][2] * i1, o[nt][3] * i1);
        *(float2*)(ob + (size_t)g * HD + c)       = w0;
        *(float2*)(ob + (size_t)(g + 8) * HD + c) = w1;
    }
}

extern "C" void kernel_launch(void* const* d_in, const int* in_sizes, int n_in,
                              void* d_out, int out_size)
{
    const float* q = (const float*)d_in[0];
    const float* k = (const float*)d_in[1];
    const float* v = (const float*)d_in[2];
    const float* m = (const float*)d_in[3];
    float* o = (float*)d_out;

    // 1) convert K/V to bf16 hi/lo persistent scratch
    prep_kernel<<<2 * (KVELEMS / 4) / 256, 256>>>(k, v);

    // 2) attention
    cudaFuncSetAttribute(fsdpa_mma, cudaFuncAttributeMaxDynamicSharedMemorySize, SMEM_BYTES);
    dim3 grid(NQ / BQ, NH);
    fsdpa_mma<<<grid, THREADS, SMEM_BYTES>>>(q, m, o);
}

// round 11
// speedup vs baseline: 1.4316x; 1.4316x over previous
#include <cuda_runtime.h>
#include <cuda_bf16.h>
#include <cstdint>

// ======================= constants =======================
#define NH      16
#define NQ      4096
#define NKV     8192
#define HD      128
#define PREFIX  (NKV - NQ)
#define BQ      64             // q rows per CTA (2 CTAs/SM)
#define BK      64
#define THREADS 128
#define LOG2E   1.4426950408889634f
#define SOFT_C  10.0f

#define KVELEMS (NH * NKV * HD)        // 16,777,216 per tensor

// bf16 tiles: 64 rows x 128 elems, row stride 272B (+16B pad, ldsm conflict-free)
#define KROW    272
#define KTILE   17408                  // 64*272
// smem layout (bytes): single buffers, temporally pipelined
#define KB0     0                      // K hi [0,17408) + lo [17408,34816)
#define VB0     34816                  // V hi + lo [34816,69632)
#define MSB0    69632                  // mask f32 64 rows x 256B [69632,86016)
#define SMEM_BYTES 86016
// Q staging scratch (prologue only): hi in K region, lo in V region
#define QSH     0
#define QSL     34816

// ======================= persistent bf16 hi/lo copies of K and V =======================
__device__ __align__(16) __nv_bfloat16 g_kh[KVELEMS];
__device__ __align__(16) __nv_bfloat16 g_kl[KVELEMS];
__device__ __align__(16) __nv_bfloat16 g_vh[KVELEMS];
__device__ __align__(16) __nv_bfloat16 g_vl[KVELEMS];

// ======================= PTX helpers (base ISA only) =======================
__device__ __forceinline__ uint32_t smem_to_u32(const void* p) {
    uint32_t a;
    asm("{ .reg .u64 t; cvta.to.shared.u64 t, %1; cvt.u32.u64 %0, t; }" : "=r"(a) : "l"(p));
    return a;
}
__device__ __forceinline__ void ldsm_x4(uint32_t addr, uint32_t* r) {
    asm volatile("ldmatrix.sync.aligned.m8n8.x4.shared.b16 {%0,%1,%2,%3}, [%4];"
                 : "=r"(r[0]), "=r"(r[1]), "=r"(r[2]), "=r"(r[3]) : "r"(addr));
}
__device__ __forceinline__ void ldsm_x4_t(uint32_t addr, uint32_t* r) {
    asm volatile("ldmatrix.sync.aligned.m8n8.x4.trans.shared.b16 {%0,%1,%2,%3}, [%4];"
                 : "=r"(r[0]), "=r"(r[1]), "=r"(r[2]), "=r"(r[3]) : "r"(addr));
}
__device__ __forceinline__ void mma_bf16(float* c, const uint32_t* a, uint32_t b0, uint32_t b1) {
    asm volatile("mma.sync.aligned.m16n8k16.row.col.f32.bf16.bf16.f32 "
                 "{%0,%1,%2,%3}, {%4,%5,%6,%7}, {%8,%9}, {%0,%1,%2,%3};"
                 : "+f"(c[0]), "+f"(c[1]), "+f"(c[2]), "+f"(c[3])
                 : "r"(a[0]), "r"(a[1]), "r"(a[2]), "r"(a[3]), "r"(b0), "r"(b1));
}
__device__ __forceinline__ uint32_t packbf(float lo, float hi) {
    uint32_t r;
    asm("cvt.rn.bf16x2.f32 %0, %1, %2;" : "=r"(r) : "f"(hi), "f"(lo));
    return r;
}
__device__ __forceinline__ float ex2f(float x) {
    float r; asm("ex2.approx.f32 %0, %1;" : "=f"(r) : "f"(x)); return r;
}
__device__ __forceinline__ void split2(float a, float b, uint32_t& hi, uint32_t& lo) {
    hi = packbf(a, b);
    float fa = __uint_as_float(hi << 16);
    float fb = __uint_as_float(hi & 0xffff0000u);
    lo = packbf(a - fa, b - fb);
}
__device__ __forceinline__ void cp_async16(uint32_t dst, const void* src) {
    asm volatile("cp.async.cg.shared.global [%0], [%1], 16;" :: "r"(dst), "l"(src) : "memory");
}
#define CP_COMMIT() asm volatile("cp.async.commit_group;" ::: "memory")
#define CP_WAIT(n)  asm volatile("cp.async.wait_group %0;" :: "n"(n) : "memory")

// ======================= prep kernel: K/V f32 -> bf16 hi/lo =======================
__global__ void __launch_bounds__(256)
prep_kernel(const float* __restrict__ K, const float* __restrict__ V)
{
    const size_t n4 = KVELEMS / 4;
    size_t i = (size_t)blockIdx.x * 256 + threadIdx.x;   // one float4 per thread
    const float* src;
    __nv_bfloat16 *dh, *dl;
    size_t j;
    if (i < n4) { src = K; dh = g_kh; dl = g_kl; j = i; }
    else        { src = V; dh = g_vh; dl = g_vl; j = i - n4; }
    float4 v = ((const float4*)src)[j];
    uint32_t h01, l01, h23, l23;
    split2(v.x, v.y, h01, l01);
    split2(v.z, v.w, h23, l23);
    ((uint2*)dh)[j] = make_uint2(h01, h23);
    ((uint2*)dl)[j] = make_uint2(l01, l23);
}

// prefetch one 64x128 bf16 tile (256B rows) into padded smem (272B rows); 128 threads
__device__ __forceinline__ void fetch_bf16_tile(uint32_t smdst, const __nv_bfloat16* gsrc, int tid) {
#pragma unroll
    for (int i = 0; i < 8; i++) {
        int gi  = tid + i * THREADS;       // 0..1023
        int row = gi >> 4, c = gi & 15;    // 16B chunks per 256B row
        cp_async16(smdst + row * KROW + c * 16, gsrc + (size_t)row * HD + c * 8);
    }
}

// ======================= main kernel =======================
__global__ void __launch_bounds__(THREADS, 2)
fsdpa_mma(const float* __restrict__ Qg, const float* __restrict__ Mg,
          float* __restrict__ Og)
{
    extern __shared__ char smem[];
    const uint32_t smb = smem_to_u32(smem);
    const int tid  = threadIdx.x;
    const int lane = tid & 31;
    const int wid  = tid >> 5;          // 0..3
    const int g    = lane >> 2;
    const int t2   = lane & 3;
    const int h    = blockIdx.y;
    const int q0   = (int)(gridDim.x - 1 - blockIdx.x) * BQ;  // longest work first
    const int wq   = wid * 16;

    const size_t kvbase = (size_t)h * NKV * HD;
    const int ntiles = (PREFIX + q0 + BQ) / BK;

    // ---- stage Q (scale folded) into scratch (K/V regions), ldmatrix to regs ----
    {
        const float scale = 0.08838834764831845f;   // 1/sqrt(128)
        const float* qb = Qg + ((size_t)h * NQ + q0) * HD;
#pragma unroll
        for (int i = 0; i < 16; i++) {
            int gi  = tid + i * THREADS;
            int row = gi >> 5, c4 = (gi & 31) << 2;
            float4 v = *(const float4*)(qb + (size_t)row * HD + c4);
            v.x *= scale; v.y *= scale; v.z *= scale; v.w *= scale;
            uint32_t h01, l01, h23, l23;
            split2(v.x, v.y, h01, l01);
            split2(v.z, v.w, h23, l23);
            int off = row * KROW + c4 * 2;
            *(uint2*)(smem + QSH + off) = make_uint2(h01, h23);
            *(uint2*)(smem + QSL + off) = make_uint2(l01, l23);
        }
    }
    __syncthreads();

    uint32_t qh[8][4], ql[8][4];
    {
        const int mi = lane >> 3;
        const uint32_t ro = (uint32_t)(wq + (lane & 7) + ((mi & 1) << 3)) * KROW + ((mi >> 1) << 4);
#pragma unroll
        for (int kc = 0; kc < 8; kc++) {
            ldsm_x4(smb + QSH + ro + kc * 32, qh[kc]);
            ldsm_x4(smb + QSL + ro + kc * 32, ql[kc]);
        }
    }
    __syncthreads();   // all ldsm reads done; K/V regions reusable

    // ---- issue K(0) + mask(0) (group A_0) ----
    fetch_bf16_tile(smb + KB0,         g_kh + kvbase, tid);
    fetch_bf16_tile(smb + KB0 + KTILE, g_kl + kvbase, tid);
#pragma unroll
    for (int i = 0; i < 8; i++) {
        int gi = tid + i * THREADS;
        int row = gi >> 4, c4 = gi & 15;
        cp_async16(smb + MSB0 + row * 256 + c4 * 16, Mg + (size_t)(q0 + row) * NKV + c4 * 4);
    }
    CP_COMMIT();

    float o[16][4];
#pragma unroll
    for (int i = 0; i < 16; i++)
#pragma unroll
        for (int j = 0; j < 4; j++) o[i][j] = 0.0f;
    float ls0 = 0.0f, ls1 = 0.0f;

    const float* msf = (const float*)(smem + MSB0);
    const float zb = -SOFT_C * LOG2E;

    for (int t = 0; t < ntiles; t++) {
        const int kv0 = t * BK;

        // top: PV(t-1) readers done with V region -> issue V(t)
        __syncthreads();
        {
            const size_t nb = kvbase + (size_t)kv0 * HD;
            fetch_bf16_tile(smb + VB0,         g_vh + nb, tid);
            fetch_bf16_tile(smb + VB0 + KTILE, g_vl + nb, tid);
        }
        CP_COMMIT();                 // group B_t (newest)
        CP_WAIT(1);                  // K(t)+mask(t) (group A_t) complete
        __syncthreads();

        // ---- S = Q @ K^T (R8 body verbatim) ----
        float s[8][4];
#pragma unroll
        for (int i = 0; i < 8; i++)
#pragma unroll
            for (int j = 0; j < 4; j++) s[i][j] = 0.0f;

#pragma unroll
        for (int kcp = 0; kcp < 4; kcp++) {
            const int kc = 2 * kcp;
#pragma unroll
            for (int ntg = 0; ntg < 4; ntg++) {
                const int nt0 = 2 * ntg, nt1 = nt0 + 1;
                const uint32_t rb0 = (uint32_t)(nt0 * 8 + (lane & 7)) * KROW
                                   + ((lane >> 3) << 4) + kcp * 64;
                const uint32_t rb1 = rb0 + 8 * KROW;
                uint32_t h0[4], l0[4], h1[4], l1[4];
                ldsm_x4(smb + KB0 + rb0,         h0);
                ldsm_x4(smb + KB0 + KTILE + rb0, l0);
                ldsm_x4(smb + KB0 + rb1,         h1);
                ldsm_x4(smb + KB0 + KTILE + rb1, l1);
                mma_bf16(s[nt0], qh[kc],     h0[0], h0[1]);
                mma_bf16(s[nt1], qh[kc],     h1[0], h1[1]);
                mma_bf16(s[nt0], qh[kc],     l0[0], l0[1]);
                mma_bf16(s[nt1], qh[kc],     l1[0], l1[1]);
                mma_bf16(s[nt0], ql[kc],     h0[0], h0[1]);
                mma_bf16(s[nt1], ql[kc],     h1[0], h1[1]);
                mma_bf16(s[nt0], qh[kc + 1], h0[2], h0[3]);
                mma_bf16(s[nt1], qh[kc + 1], h1[2], h1[3]);
                mma_bf16(s[nt0], qh[kc + 1], l0[2], l0[3]);
                mma_bf16(s[nt1], qh[kc + 1], l1[2], l1[3]);
                mma_bf16(s[nt0], ql[kc + 1], h0[2], h0[3]);
                mma_bf16(s[nt1], ql[kc + 1], h1[2], h1[3]);
            }
        }

        // ---- softmax (fixed shift) ----
        {
            const int  lim0 = PREFIX + q0 + wq + g - kv0;
            const int  lim1 = lim0 + 8;
            const bool dg   = (t >= ntiles - 1);   // BQ==BK: only last tile is diagonal
            const float* mrow0 = msf + (wq + g) * 64;
            const float* mrow1 = mrow0 + 8 * 64;
#pragma unroll
            for (int nt = 0; nt < 8; nt++) {
                const int c = nt * 8 + t2 * 2;
                float2 m0 = *(const float2*)(mrow0 + c);
                float2 m1 = *(const float2*)(mrow1 + c);
                float z00 = fmaf(s[nt][0] + m0.x, LOG2E, zb);
                float z01 = fmaf(s[nt][1] + m0.y, LOG2E, zb);
                float z10 = fmaf(s[nt][2] + m1.x, LOG2E, zb);
                float z11 = fmaf(s[nt][3] + m1.y, LOG2E, zb);
                if (dg) {
                    if (c     > lim0) z00 = -127.0f;
                    if (c + 1 > lim0) z01 = -127.0f;
                    if (c     > lim1) z10 = -127.0f;
                    if (c + 1 > lim1) z11 = -127.0f;
                }
                float p00 = ex2f(z00), p01 = ex2f(z01);
                float p10 = ex2f(z10), p11 = ex2f(z11);
                ls0 += p00 + p01;
                ls1 += p10 + p11;
                s[nt][0] = p00; s[nt][1] = p01; s[nt][2] = p10; s[nt][3] = p11;
            }
        }

        // mid: K(t)/mask(t) readers done -> issue K(t+1)+mask(t+1)
        __syncthreads();
        if (t + 1 < ntiles) {
            const size_t nb = kvbase + (size_t)(kv0 + BK) * HD;
            fetch_bf16_tile(smb + KB0,         g_kh + nb, tid);
            fetch_bf16_tile(smb + KB0 + KTILE, g_kl + nb, tid);
#pragma unroll
            for (int i = 0; i < 8; i++) {
                int gi = tid + i * THREADS;
                int row = gi >> 4, c4 = gi & 15;
                cp_async16(smb + MSB0 + row * 256 + c4 * 16,
                           Mg + (size_t)(q0 + row) * NKV + (kv0 + BK) + c4 * 4);
            }
        }
        CP_COMMIT();                 // group A_{t+1} (possibly empty; newest)
        CP_WAIT(1);                  // V(t) (group B_t) complete
        __syncthreads();

        // ---- O += P @ V (R8 body verbatim) ----
#pragma unroll
        for (int kc = 0; kc < 4; kc++) {
            uint32_t ah[4], al[4];
            split2(s[2 * kc][0],     s[2 * kc][1],     ah[0], al[0]);
            split2(s[2 * kc][2],     s[2 * kc][3],     ah[1], al[1]);
            split2(s[2 * kc + 1][0], s[2 * kc + 1][1], ah[2], al[2]);
            split2(s[2 * kc + 1][2], s[2 * kc + 1][3], ah[3], al[3]);
            const uint32_t rv = (uint32_t)(kc * 16 + ((lane >> 3) & 1) * 8 + (lane & 7)) * KROW
                              + ((lane >> 4) << 4);
#pragma unroll
            for (int pg = 0; pg < 4; pg++) {
                const int p0 = 2 * pg, p1 = p0 + 1;
                uint32_t vh0[4], vl0[4], vh1[4], vl1[4];
                ldsm_x4_t(smb + VB0 + rv + p0 * 32,         vh0);
                ldsm_x4_t(smb + VB0 + KTILE + rv + p0 * 32, vl0);
                ldsm_x4_t(smb + VB0 + rv + p1 * 32,         vh1);
                ldsm_x4_t(smb + VB0 + KTILE + rv + p1 * 32, vl1);
                mma_bf16(o[2 * p0],     ah, vh0[0], vh0[1]);
                mma_bf16(o[2 * p0 + 1], ah, vh0[2], vh0[3]);
                mma_bf16(o[2 * p1],     ah, vh1[0], vh1[1]);
                mma_bf16(o[2 * p1 + 1], ah, vh1[2], vh1[3]);
                mma_bf16(o[2 * p0],     ah, vl0[0], vl0[1]);
                mma_bf16(o[2 * p0 + 1], ah, vl0[2], vl0[3]);
                mma_bf16(o[2 * p1],     ah, vl1[0], vl1[1]);
                mma_bf16(o[2 * p1 + 1], ah, vl1[2], vl1[3]);
                mma_bf16(o[2 * p0],     al, vh0[0], vh0[1]);
                mma_bf16(o[2 * p0 + 1], al, vh0[2], vh0[3]);
                mma_bf16(o[2 * p1],     al, vh1[0], vh1[1]);
                mma_bf16(o[2 * p1 + 1], al, vh1[2], vh1[3]);
            }
        }
    }

    // ---- epilogue ----
    ls0 += __shfl_xor_sync(0xffffffffu, ls0, 1);
    ls0 += __shfl_xor_sync(0xffffffffu, ls0, 2);
    ls1 += __shfl_xor_sync(0xffffffffu, ls1, 1);
    ls1 += __shfl_xor_sync(0xffffffffu, ls1, 2);
    const float i0 = 1.0f / ls0;
    const float i1 = 1.0f / ls1;

    float* ob = Og + ((size_t)h * NQ + q0 + wq) * HD;
#pragma unroll
    for (int nt = 0; nt < 16; nt++) {
        const int c = nt * 8 + t2 * 2;
        float2 w0 = make_float2(o[nt][0] * i0, o[nt][1] * i0);
        float2 w1 = make_float2(o[nt][2] * i1, o[nt][3] * i1);
        *(float2*)(ob + (size_t)g * HD + c)       = w0;
        *(float2*)(ob + (size_t)(g + 8) * HD + c) = w1;
    }
}

extern "C" void kernel_launch(void* const* d_in, const int* in_sizes, int n_in,
                              void* d_out, int out_size)
{
    const float* q = (const float*)d_in[0];
    const float* k = (const float*)d_in[1];
    const float* v = (const float*)d_in[2];
    const float* m = (const float*)d_in[3];
    float* o = (float*)d_out;

    // 1) convert K/V to bf16 hi/lo persistent scratch
    prep_kernel<<<2 * (KVELEMS / 4) / 256, 256>>>(k, v);

    // 2) attention: 128-thread CTAs, 2 resident per SM
    cudaFuncSetAttribute(fsdpa_mma, cudaFuncAttributeMaxDynamicSharedMemorySize, SMEM_BYTES);
    dim3 grid(NQ / BQ, NH);
    fsdpa_mma<<<grid, THREADS, SMEM_BYTES>>>(q, m, o);
}

// round 12
// speedup vs baseline: 1.4809x; 1.0344x over previous
#include <cuda_runtime.h>
#include <cuda_bf16.h>
#include <cstdint>

// ======================= constants =======================
#define NH      16
#define NQ      4096
#define NKV     8192
#define HD      128
#define PREFIX  (NKV - NQ)
#define BQ      64             // q rows per CTA (2 CTAs/SM)
#define BK      64
#define THREADS 128
#define LOG2E   1.4426950408889634f
#define SOFT_C  10.0f

#define KVELEMS (NH * NKV * HD)        // 16,777,216 per tensor

// bf16 tiles: 64 rows x 128 elems, row stride 272B (+16B pad, ldsm conflict-free)
#define KROW    272
#define KTILE   17408                  // 64*272
// smem layout (bytes): single buffers, temporally pipelined
#define KB0     0                      // K hi [0,17408) + lo [17408,34816)
#define VB0     34816                  // V hi + lo [34816,69632)
#define MSB0    69632                  // mask f32 64 rows x 256B [69632,86016)
#define SMEM_BYTES 86016
// Q staging scratch (prologue only): hi in K region, lo in V region
#define QSH     0
#define QSL     34816

// ======================= persistent bf16 hi/lo copies of K and V =======================
__device__ __align__(16) __nv_bfloat16 g_kh[KVELEMS];
__device__ __align__(16) __nv_bfloat16 g_kl[KVELEMS];
__device__ __align__(16) __nv_bfloat16 g_vh[KVELEMS];
__device__ __align__(16) __nv_bfloat16 g_vl[KVELEMS];

// ======================= PTX helpers (base ISA only) =======================
__device__ __forceinline__ uint32_t smem_to_u32(const void* p) {
    uint32_t a;
    asm("{ .reg .u64 t; cvta.to.shared.u64 t, %1; cvt.u32.u64 %0, t; }" : "=r"(a) : "l"(p));
    return a;
}
__device__ __forceinline__ void ldsm_x4(uint32_t addr, uint32_t* r) {
    asm volatile("ldmatrix.sync.aligned.m8n8.x4.shared.b16 {%0,%1,%2,%3}, [%4];"
                 : "=r"(r[0]), "=r"(r[1]), "=r"(r[2]), "=r"(r[3]) : "r"(addr));
}
__device__ __forceinline__ void ldsm_x4_t(uint32_t addr, uint32_t* r) {
    asm volatile("ldmatrix.sync.aligned.m8n8.x4.trans.shared.b16 {%0,%1,%2,%3}, [%4];"
                 : "=r"(r[0]), "=r"(r[1]), "=r"(r[2]), "=r"(r[3]) : "r"(addr));
}
__device__ __forceinline__ void mma_bf16(float* c, const uint32_t* a, uint32_t b0, uint32_t b1) {
    asm volatile("mma.sync.aligned.m16n8k16.row.col.f32.bf16.bf16.f32 "
                 "{%0,%1,%2,%3}, {%4,%5,%6,%7}, {%8,%9}, {%0,%1,%2,%3};"
                 : "+f"(c[0]), "+f"(c[1]), "+f"(c[2]), "+f"(c[3])
                 : "r"(a[0]), "r"(a[1]), "r"(a[2]), "r"(a[3]), "r"(b0), "r"(b1));
}
__device__ __forceinline__ uint32_t packbf(float lo, float hi) {
    uint32_t r;
    asm("cvt.rn.bf16x2.f32 %0, %1, %2;" : "=r"(r) : "f"(hi), "f"(lo));
    return r;
}
__device__ __forceinline__ float ex2f(float x) {
    float r; asm("ex2.approx.f32 %0, %1;" : "=f"(r) : "f"(x)); return r;
}
__device__ __forceinline__ void split2(float a, float b, uint32_t& hi, uint32_t& lo) {
    hi = packbf(a, b);
    float fa = __uint_as_float(hi << 16);
    float fb = __uint_as_float(hi & 0xffff0000u);
    lo = packbf(a - fa, b - fb);
}
__device__ __forceinline__ void cp_async16(uint32_t dst, const void* src) {
    asm volatile("cp.async.cg.shared.global [%0], [%1], 16;" :: "r"(dst), "l"(src) : "memory");
}
#define CP_COMMIT() asm volatile("cp.async.commit_group;" ::: "memory")
#define CP_WAIT(n)  asm volatile("cp.async.wait_group %0;" :: "n"(n) : "memory")

// ======================= prep kernel: K/V f32 -> bf16 hi/lo =======================
__global__ void __launch_bounds__(256)
prep_kernel(const float* __restrict__ K, const float* __restrict__ V)
{
    const size_t n4 = KVELEMS / 4;
    size_t i = (size_t)blockIdx.x * 256 + threadIdx.x;   // one float4 per thread
    const float* src;
    __nv_bfloat16 *dh, *dl;
    size_t j;
    if (i < n4) { src = K; dh = g_kh; dl = g_kl; j = i; }
    else        { src = V; dh = g_vh; dl = g_vl; j = i - n4; }
    float4 v = ((const float4*)src)[j];
    uint32_t h01, l01, h23, l23;
    split2(v.x, v.y, h01, l01);
    split2(v.z, v.w, h23, l23);
    ((uint2*)dh)[j] = make_uint2(h01, h23);
    ((uint2*)dl)[j] = make_uint2(l01, l23);
}

// prefetch one 64x128 bf16 tile (256B rows) into padded smem (272B rows); 128 threads
__device__ __forceinline__ void fetch_bf16_tile(uint32_t smdst, const __nv_bfloat16* gsrc, int tid) {
#pragma unroll
    for (int i = 0; i < 8; i++) {
        int gi  = tid + i * THREADS;       // 0..1023
        int row = gi >> 4, c = gi & 15;    // 16B chunks per 256B row
        cp_async16(smdst + row * KROW + c * 16, gsrc + (size_t)row * HD + c * 8);
    }
}

// ======================= main kernel =======================
__global__ void __launch_bounds__(THREADS, 2)
fsdpa_mma(const float* __restrict__ Qg, const float* __restrict__ Mg,
          float* __restrict__ Og)
{
    extern __shared__ char smem[];
    const uint32_t smb = smem_to_u32(smem);
    const int tid  = threadIdx.x;
    const int lane = tid & 31;
    const int wid  = tid >> 5;          // 0..3
    const int g    = lane >> 2;
    const int t2   = lane & 3;
    const int h    = blockIdx.y;
    const int q0   = (int)(gridDim.x - 1 - blockIdx.x) * BQ;  // longest work first
    const int wq   = wid * 16;

    const size_t kvbase = (size_t)h * NKV * HD;
    const int ntiles = (PREFIX + q0 + BQ) / BK;

    // ---- stage Q (scale folded) into scratch (K/V regions), ldmatrix to regs ----
    {
        const float scale = 0.08838834764831845f;   // 1/sqrt(128)
        const float* qb = Qg + ((size_t)h * NQ + q0) * HD;
#pragma unroll
        for (int i = 0; i < 16; i++) {
            int gi  = tid + i * THREADS;
            int row = gi >> 5, c4 = (gi & 31) << 2;
            float4 v = *(const float4*)(qb + (size_t)row * HD + c4);
            v.x *= scale; v.y *= scale; v.z *= scale; v.w *= scale;
            uint32_t h01, l01, h23, l23;
            split2(v.x, v.y, h01, l01);
            split2(v.z, v.w, h23, l23);
            int off = row * KROW + c4 * 2;
            *(uint2*)(smem + QSH + off) = make_uint2(h01, h23);
            *(uint2*)(smem + QSL + off) = make_uint2(l01, l23);
        }
    }
    __syncthreads();

    uint32_t qh[8][4], ql[8][4];
    {
        const int mi = lane >> 3;
        const uint32_t ro = (uint32_t)(wq + (lane & 7) + ((mi & 1) << 3)) * KROW + ((mi >> 1) << 4);
#pragma unroll
        for (int kc = 0; kc < 8; kc++) {
            ldsm_x4(smb + QSH + ro + kc * 32, qh[kc]);
            ldsm_x4(smb + QSL + ro + kc * 32, ql[kc]);
        }
    }
    __syncthreads();   // all ldsm reads done; K/V regions reusable

    // ---- issue K(0) + mask(0) (group A_0) ----
    fetch_bf16_tile(smb + KB0,         g_kh + kvbase, tid);
    fetch_bf16_tile(smb + KB0 + KTILE, g_kl + kvbase, tid);
#pragma unroll
    for (int i = 0; i < 8; i++) {
        int gi = tid + i * THREADS;
        int row = gi >> 4, c4 = gi & 15;
        cp_async16(smb + MSB0 + row * 256 + c4 * 16, Mg + (size_t)(q0 + row) * NKV + c4 * 4);
    }
    CP_COMMIT();

    float o[16][4];
#pragma unroll
    for (int i = 0; i < 16; i++)
#pragma unroll
        for (int j = 0; j < 4; j++) o[i][j] = 0.0f;
    float ls0 = 0.0f, ls1 = 0.0f;

    const float* msf = (const float*)(smem + MSB0);
    const float zb = -SOFT_C * LOG2E;

    for (int t = 0; t < ntiles; t++) {
        const int kv0 = t * BK;

        // top: PV(t-1) readers done with V region -> issue V(t)
        __syncthreads();
        {
            const size_t nb = kvbase + (size_t)kv0 * HD;
            fetch_bf16_tile(smb + VB0,         g_vh + nb, tid);
            fetch_bf16_tile(smb + VB0 + KTILE, g_vl + nb, tid);
        }
        CP_COMMIT();                 // group B_t (newest)
        CP_WAIT(1);                  // K(t)+mask(t) (group A_t) complete
        __syncthreads();

        // ---- S = Q @ K^T: 4-accumulator rotation (same-acc gap = 4 MMAs) ----
        float s[8][4];
#pragma unroll
        for (int i = 0; i < 8; i++)
#pragma unroll
            for (int j = 0; j < 4; j++) s[i][j] = 0.0f;

#pragma unroll
        for (int kcp = 0; kcp < 4; kcp++) {
            const int kc = 2 * kcp;
#pragma unroll
            for (int half = 0; half < 2; half++) {
                const int ntb = 4 * half;
                uint32_t fh[4][4], fl[4][4];
#pragma unroll
                for (int j = 0; j < 4; j++) {
                    const uint32_t rb = (uint32_t)((ntb + j) * 8 + (lane & 7)) * KROW
                                      + ((lane >> 3) << 4) + kcp * 64;
                    ldsm_x4(smb + KB0 + rb,         fh[j]);
                    ldsm_x4(smb + KB0 + KTILE + rb, fl[j]);
                }
                // 24 MMAs, term-major, rotating over 4 accumulators
#pragma unroll
                for (int j = 0; j < 4; j++) mma_bf16(s[ntb + j], qh[kc],     fh[j][0], fh[j][1]);
#pragma unroll
                for (int j = 0; j < 4; j++) mma_bf16(s[ntb + j], qh[kc],     fl[j][0], fl[j][1]);
#pragma unroll
                for (int j = 0; j < 4; j++) mma_bf16(s[ntb + j], ql[kc],     fh[j][0], fh[j][1]);
#pragma unroll
                for (int j = 0; j < 4; j++) mma_bf16(s[ntb + j], qh[kc + 1], fh[j][2], fh[j][3]);
#pragma unroll
                for (int j = 0; j < 4; j++) mma_bf16(s[ntb + j], qh[kc + 1], fl[j][2], fl[j][3]);
#pragma unroll
                for (int j = 0; j < 4; j++) mma_bf16(s[ntb + j], ql[kc + 1], fh[j][2], fh[j][3]);
            }
        }

        // ---- softmax (fixed shift) ----
        {
            const int  lim0 = PREFIX + q0 + wq + g - kv0;
            const int  lim1 = lim0 + 8;
            const bool dg   = (t >= ntiles - 1);   // BQ==BK: only last tile is diagonal
            const float* mrow0 = msf + (wq + g) * 64;
            const float* mrow1 = mrow0 + 8 * 64;
#pragma unroll
            for (int nt = 0; nt < 8; nt++) {
                const int c = nt * 8 + t2 * 2;
                float2 m0 = *(const float2*)(mrow0 + c);
                float2 m1 = *(const float2*)(mrow1 + c);
                float z00 = fmaf(s[nt][0] + m0.x, LOG2E, zb);
                float z01 = fmaf(s[nt][1] + m0.y, LOG2E, zb);
                float z10 = fmaf(s[nt][2] + m1.x, LOG2E, zb);
                float z11 = fmaf(s[nt][3] + m1.y, LOG2E, zb);
                if (dg) {
                    if (c     > lim0) z00 = -127.0f;
                    if (c + 1 > lim0) z01 = -127.0f;
                    if (c     > lim1) z10 = -127.0f;
                    if (c + 1 > lim1) z11 = -127.0f;
                }
                float p00 = ex2f(z00), p01 = ex2f(z01);
                float p10 = ex2f(z10), p11 = ex2f(z11);
                ls0 += p00 + p01;
                ls1 += p10 + p11;
                s[nt][0] = p00; s[nt][1] = p01; s[nt][2] = p10; s[nt][3] = p11;
            }
        }

        // mid: K(t)/mask(t) readers done -> issue K(t+1)+mask(t+1)
        __syncthreads();
        if (t + 1 < ntiles) {
            const size_t nb = kvbase + (size_t)(kv0 + BK) * HD;
            fetch_bf16_tile(smb + KB0,         g_kh + nb, tid);
            fetch_bf16_tile(smb + KB0 + KTILE, g_kl + nb, tid);
#pragma unroll
            for (int i = 0; i < 8; i++) {
                int gi = tid + i * THREADS;
                int row = gi >> 4, c4 = gi & 15;
                cp_async16(smb + MSB0 + row * 256 + c4 * 16,
                           Mg + (size_t)(q0 + row) * NKV + (kv0 + BK) + c4 * 4);
            }
        }
        CP_COMMIT();                 // group A_{t+1} (possibly empty; newest)
        CP_WAIT(1);                  // V(t) (group B_t) complete
        __syncthreads();

        // ---- O += P @ V (4-acc rotation, unchanged) ----
#pragma unroll
        for (int kc = 0; kc < 4; kc++) {
            uint32_t ah[4], al[4];
            split2(s[2 * kc][0],     s[2 * kc][1],     ah[0], al[0]);
            split2(s[2 * kc][2],     s[2 * kc][3],     ah[1], al[1]);
            split2(s[2 * kc + 1][0], s[2 * kc + 1][1], ah[2], al[2]);
            split2(s[2 * kc + 1][2], s[2 * kc + 1][3], ah[3], al[3]);
            const uint32_t rv = (uint32_t)(kc * 16 + ((lane >> 3) & 1) * 8 + (lane & 7)) * KROW
                              + ((lane >> 4) << 4);
#pragma unroll
            for (int pg = 0; pg < 4; pg++) {
                const int p0 = 2 * pg, p1 = p0 + 1;
                uint32_t vh0[4], vl0[4], vh1[4], vl1[4];
                ldsm_x4_t(smb + VB0 + rv + p0 * 32,         vh0);
                ldsm_x4_t(smb + VB0 + KTILE + rv + p0 * 32, vl0);
                ldsm_x4_t(smb + VB0 + rv + p1 * 32,         vh1);
                ldsm_x4_t(smb + VB0 + KTILE + rv + p1 * 32, vl1);
                mma_bf16(o[2 * p0],     ah, vh0[0], vh0[1]);
                mma_bf16(o[2 * p0 + 1], ah, vh0[2], vh0[3]);
                mma_bf16(o[2 * p1],     ah, vh1[0], vh1[1]);
                mma_bf16(o[2 * p1 + 1], ah, vh1[2], vh1[3]);
                mma_bf16(o[2 * p0],     ah, vl0[0], vl0[1]);
                mma_bf16(o[2 * p0 + 1], ah, vl0[2], vl0[3]);
                mma_bf16(o[2 * p1],     ah, vl1[0], vl1[1]);
                mma_bf16(o[2 * p1 + 1], ah, vl1[2], vl1[3]);
                mma_bf16(o[2 * p0],     al, vh0[0], vh0[1]);
                mma_bf16(o[2 * p0 + 1], al, vh0[2], vh0[3]);
                mma_bf16(o[2 * p1],     al, vh1[0], vh1[1]);
                mma_bf16(o[2 * p1 + 1], al, vh1[2], vh1[3]);
            }
        }
    }

    // ---- epilogue ----
    ls0 += __shfl_xor_sync(0xffffffffu, ls0, 1);
    ls0 += __shfl_xor_sync(0xffffffffu, ls0, 2);
    ls1 += __shfl_xor_sync(0xffffffffu, ls1, 1);
    ls1 += __shfl_xor_sync(0xffffffffu, ls1, 2);
    const float i0 = 1.0f / ls0;
    const float i1 = 1.0f / ls1;

    float* ob = Og + ((size_t)h * NQ + q0 + wq) * HD;
#pragma unroll
    for (int nt = 0; nt < 16; nt++) {
        const int c = nt * 8 + t2 * 2;
        float2 w0 = make_float2(o[nt][0] * i0, o[nt][1] * i0);
        float2 w1 = make_float2(o[nt][2] * i1, o[nt][3] * i1);
        *(float2*)(ob + (size_t)g * HD + c)       = w0;
        *(float2*)(ob + (size_t)(g + 8) * HD + c) = w1;
    }
}

extern "C" void kernel_launch(void* const* d_in, const int* in_sizes, int n_in,
                              void* d_out, int out_size)
{
    const float* q = (const float*)d_in[0];
    const float* k = (const float*)d_in[1];
    const float* v = (const float*)d_in[2];
    const float* m = (const float*)d_in[3];
    float* o = (float*)d_out;

    // 1) convert K/V to bf16 hi/lo persistent scratch
    prep_kernel<<<2 * (KVELEMS / 4) / 256, 256>>>(k, v);

    // 2) attention: 128-thread CTAs, 2 resident per SM
    cudaFuncSetAttribute(fsdpa_mma, cudaFuncAttributeMaxDynamicSharedMemorySize, SMEM_BYTES);
    dim3 grid(NQ / BQ, NH);
    fsdpa_mma<<<grid, THREADS, SMEM_BYTES>>>(q, m, o);
}

// round 13
// speedup vs baseline: 1.4966x; 1.0106x over previous
#include <cuda_runtime.h>
#include <cuda_bf16.h>
#include <cstdint>

// ======================= constants =======================
#define NH      16
#define NQ      4096
#define NKV     8192
#define HD      128
#define PREFIX  (NKV - NQ)
#define BQ      64             // q rows per CTA (2 CTAs/SM)
#define BK      64
#define THREADS 128
#define LOG2E   1.4426950408889634f
#define SOFT_C  10.0f

#define KVELEMS (NH * NKV * HD)        // 16,777,216 per tensor

// bf16 tiles: 64 rows x 128 elems, row stride 272B (+16B pad, ldsm conflict-free)
#define KROW    272
#define KTILE   17408                  // 64*272
// smem layout (bytes): single buffers, temporally pipelined
#define KB0     0                      // K hi [0,17408) + lo [17408,34816)
#define VB0     34816                  // V hi + lo [34816,69632)
#define MSB0    69632                  // mask f32 64 rows x 256B [69632,86016)
#define SMEM_BYTES 86016
// Q staging scratch (prologue only): hi in K region, lo in V region
#define QSH     0
#define QSL     34816

// ======================= persistent bf16 hi/lo copies of K and V =======================
__device__ __align__(16) __nv_bfloat16 g_kh[KVELEMS];
__device__ __align__(16) __nv_bfloat16 g_kl[KVELEMS];
__device__ __align__(16) __nv_bfloat16 g_vh[KVELEMS];
__device__ __align__(16) __nv_bfloat16 g_vl[KVELEMS];

// ======================= PTX helpers (base ISA only) =======================
__device__ __forceinline__ uint32_t smem_to_u32(const void* p) {
    uint32_t a;
    asm("{ .reg .u64 t; cvta.to.shared.u64 t, %1; cvt.u32.u64 %0, t; }" : "=r"(a) : "l"(p));
    return a;
}
__device__ __forceinline__ void ldsm_x4(uint32_t addr, uint32_t* r) {
    asm volatile("ldmatrix.sync.aligned.m8n8.x4.shared.b16 {%0,%1,%2,%3}, [%4];"
                 : "=r"(r[0]), "=r"(r[1]), "=r"(r[2]), "=r"(r[3]) : "r"(addr));
}
__device__ __forceinline__ void ldsm_x4_t(uint32_t addr, uint32_t* r) {
    asm volatile("ldmatrix.sync.aligned.m8n8.x4.trans.shared.b16 {%0,%1,%2,%3}, [%4];"
                 : "=r"(r[0]), "=r"(r[1]), "=r"(r[2]), "=r"(r[3]) : "r"(addr));
}
__device__ __forceinline__ void mma_bf16(float* c, const uint32_t* a, uint32_t b0, uint32_t b1) {
    asm volatile("mma.sync.aligned.m16n8k16.row.col.f32.bf16.bf16.f32 "
                 "{%0,%1,%2,%3}, {%4,%5,%6,%7}, {%8,%9}, {%0,%1,%2,%3};"
                 : "+f"(c[0]), "+f"(c[1]), "+f"(c[2]), "+f"(c[3])
                 : "r"(a[0]), "r"(a[1]), "r"(a[2]), "r"(a[3]), "r"(b0), "r"(b1));
}
__device__ __forceinline__ uint32_t packbf(float lo, float hi) {
    uint32_t r;
    asm("cvt.rn.bf16x2.f32 %0, %1, %2;" : "=r"(r) : "f"(hi), "f"(lo));
    return r;
}
__device__ __forceinline__ float ex2f(float x) {
    float r; asm("ex2.approx.f32 %0, %1;" : "=f"(r) : "f"(x)); return r;
}
__device__ __forceinline__ void split2(float a, float b, uint32_t& hi, uint32_t& lo) {
    hi = packbf(a, b);
    float fa = __uint_as_float(hi << 16);
    float fb = __uint_as_float(hi & 0xffff0000u);
    lo = packbf(a - fa, b - fb);
}
__device__ __forceinline__ void cp_async16(uint32_t dst, const void* src) {
    asm volatile("cp.async.cg.shared.global [%0], [%1], 16;" :: "r"(dst), "l"(src) : "memory");
}
#define CP_COMMIT() asm volatile("cp.async.commit_group;" ::: "memory")
#define CP_WAIT(n)  asm volatile("cp.async.wait_group %0;" :: "n"(n) : "memory")

// ======================= prep kernel: K/V f32 -> bf16 hi/lo =======================
__global__ void __launch_bounds__(256)
prep_kernel(const float* __restrict__ K, const float* __restrict__ V)
{
    const size_t n4 = KVELEMS / 4;
    size_t i = (size_t)blockIdx.x * 256 + threadIdx.x;   // one float4 per thread
    const float* src;
    __nv_bfloat16 *dh, *dl;
    size_t j;
    if (i < n4) { src = K; dh = g_kh; dl = g_kl; j = i; }
    else        { src = V; dh = g_vh; dl = g_vl; j = i - n4; }
    float4 v = ((const float4*)src)[j];
    uint32_t h01, l01, h23, l23;
    split2(v.x, v.y, h01, l01);
    split2(v.z, v.w, h23, l23);
    ((uint2*)dh)[j] = make_uint2(h01, h23);
    ((uint2*)dl)[j] = make_uint2(l01, l23);
}

// prefetch one 64x128 bf16 tile (256B rows) into padded smem (272B rows); 128 threads
__device__ __forceinline__ void fetch_bf16_tile(uint32_t smdst, const __nv_bfloat16* gsrc, int tid) {
#pragma unroll
    for (int i = 0; i < 8; i++) {
        int gi  = tid + i * THREADS;       // 0..1023
        int row = gi >> 4, c = gi & 15;    // 16B chunks per 256B row
        cp_async16(smdst + row * KROW + c * 16, gsrc + (size_t)row * HD + c * 8);
    }
}

// ======================= main kernel =======================
__global__ void __launch_bounds__(THREADS, 2)
fsdpa_mma(const float* __restrict__ Qg, const float* __restrict__ Mg,
          float* __restrict__ Og)
{
    extern __shared__ char smem[];
    const uint32_t smb = smem_to_u32(smem);
    const int tid  = threadIdx.x;
    const int lane = tid & 31;
    const int wid  = tid >> 5;          // 0..3
    const int g    = lane >> 2;
    const int t2   = lane & 3;
    const int h    = blockIdx.y;
    const int q0   = (int)(gridDim.x - 1 - blockIdx.x) * BQ;  // longest work first
    const int wq   = wid * 16;

    const size_t kvbase = (size_t)h * NKV * HD;
    const int ntiles = (PREFIX + q0 + BQ) / BK;

    // ---- stage Q (scale folded) into scratch (K/V regions), ldmatrix to regs ----
    {
        const float scale = 0.08838834764831845f;   // 1/sqrt(128)
        const float* qb = Qg + ((size_t)h * NQ + q0) * HD;
#pragma unroll
        for (int i = 0; i < 16; i++) {
            int gi  = tid + i * THREADS;
            int row = gi >> 5, c4 = (gi & 31) << 2;
            float4 v = *(const float4*)(qb + (size_t)row * HD + c4);
            v.x *= scale; v.y *= scale; v.z *= scale; v.w *= scale;
            uint32_t h01, l01, h23, l23;
            split2(v.x, v.y, h01, l01);
            split2(v.z, v.w, h23, l23);
            int off = row * KROW + c4 * 2;
            *(uint2*)(smem + QSH + off) = make_uint2(h01, h23);
            *(uint2*)(smem + QSL + off) = make_uint2(l01, l23);
        }
    }
    __syncthreads();

    uint32_t qh[8][4], ql[8][4];
    {
        const int mi = lane >> 3;
        const uint32_t ro = (uint32_t)(wq + (lane & 7) + ((mi & 1) << 3)) * KROW + ((mi >> 1) << 4);
#pragma unroll
        for (int kc = 0; kc < 8; kc++) {
            ldsm_x4(smb + QSH + ro + kc * 32, qh[kc]);
            ldsm_x4(smb + QSL + ro + kc * 32, ql[kc]);
        }
    }
    __syncthreads();   // all ldsm reads done; K/V regions reusable

    // ---- issue K(0) + mask(0) (group A_0) ----
    fetch_bf16_tile(smb + KB0,         g_kh + kvbase, tid);
    fetch_bf16_tile(smb + KB0 + KTILE, g_kl + kvbase, tid);
#pragma unroll
    for (int i = 0; i < 8; i++) {
        int gi = tid + i * THREADS;
        int row = gi >> 4, c4 = gi & 15;
        cp_async16(smb + MSB0 + row * 256 + c4 * 16, Mg + (size_t)(q0 + row) * NKV + c4 * 4);
    }
    CP_COMMIT();

    float o[16][4];
#pragma unroll
    for (int i = 0; i < 16; i++)
#pragma unroll
        for (int j = 0; j < 4; j++) o[i][j] = 0.0f;
    float ls0 = 0.0f, ls1 = 0.0f;

    const float* msf = (const float*)(smem + MSB0);
    const float zb = -SOFT_C * LOG2E;

    for (int t = 0; t < ntiles; t++) {
        const int kv0 = t * BK;

        // top: PV(t-1) readers done with V region -> issue V(t)
        __syncthreads();
        {
            const size_t nb = kvbase + (size_t)kv0 * HD;
            fetch_bf16_tile(smb + VB0,         g_vh + nb, tid);
            fetch_bf16_tile(smb + VB0 + KTILE, g_vl + nb, tid);
        }
        CP_COMMIT();                 // group B_t (newest)
        CP_WAIT(1);                  // K(t)+mask(t) (group A_t) complete
        __syncthreads();

        // ---- S = Q @ K^T: 4-accumulator rotation (same-acc gap = 4 MMAs) ----
        float s[8][4];
#pragma unroll
        for (int i = 0; i < 8; i++)
#pragma unroll
            for (int j = 0; j < 4; j++) s[i][j] = 0.0f;

#pragma unroll
        for (int kcp = 0; kcp < 4; kcp++) {
            const int kc = 2 * kcp;
#pragma unroll
            for (int half = 0; half < 2; half++) {
                const int ntb = 4 * half;
                uint32_t fh[4][4], fl[4][4];
#pragma unroll
                for (int j = 0; j < 4; j++) {
                    const uint32_t rb = (uint32_t)((ntb + j) * 8 + (lane & 7)) * KROW
                                      + ((lane >> 3) << 4) + kcp * 64;
                    ldsm_x4(smb + KB0 + rb,         fh[j]);
                    ldsm_x4(smb + KB0 + KTILE + rb, fl[j]);
                }
#pragma unroll
                for (int j = 0; j < 4; j++) mma_bf16(s[ntb + j], qh[kc],     fh[j][0], fh[j][1]);
#pragma unroll
                for (int j = 0; j < 4; j++) mma_bf16(s[ntb + j], qh[kc],     fl[j][0], fl[j][1]);
#pragma unroll
                for (int j = 0; j < 4; j++) mma_bf16(s[ntb + j], ql[kc],     fh[j][0], fh[j][1]);
#pragma unroll
                for (int j = 0; j < 4; j++) mma_bf16(s[ntb + j], qh[kc + 1], fh[j][2], fh[j][3]);
#pragma unroll
                for (int j = 0; j < 4; j++) mma_bf16(s[ntb + j], qh[kc + 1], fl[j][2], fl[j][3]);
#pragma unroll
                for (int j = 0; j < 4; j++) mma_bf16(s[ntb + j], ql[kc + 1], fh[j][2], fh[j][3]);
            }
        }

        // ---- softmax phase A (serial, cheap): s += mask, causal sentinel ----
        {
            const int  lim0 = PREFIX + q0 + wq + g - kv0;
            const int  lim1 = lim0 + 8;
            const bool dg   = (t >= ntiles - 1);   // BQ==BK: only last tile is diagonal
            const float* mrow0 = msf + (wq + g) * 64;
            const float* mrow1 = mrow0 + 8 * 64;
#pragma unroll
            for (int nt = 0; nt < 8; nt++) {
                const int c = nt * 8 + t2 * 2;
                float2 m0 = *(const float2*)(mrow0 + c);
                float2 m1 = *(const float2*)(mrow1 + c);
                s[nt][0] += m0.x;
                s[nt][1] += m0.y;
                s[nt][2] += m1.x;
                s[nt][3] += m1.y;
                if (dg) {
                    if (c     > lim0) s[nt][0] = -200.0f;
                    if (c + 1 > lim0) s[nt][1] = -200.0f;
                    if (c     > lim1) s[nt][2] = -200.0f;
                    if (c + 1 > lim1) s[nt][3] = -200.0f;
                }
            }
        }

        // mid: K(t)/mask(t) readers done -> issue K(t+1)+mask(t+1)
        __syncthreads();
        if (t + 1 < ntiles) {
            const size_t nb = kvbase + (size_t)(kv0 + BK) * HD;
            fetch_bf16_tile(smb + KB0,         g_kh + nb, tid);
            fetch_bf16_tile(smb + KB0 + KTILE, g_kl + nb, tid);
#pragma unroll
            for (int i = 0; i < 8; i++) {
                int gi = tid + i * THREADS;
                int row = gi >> 4, c4 = gi & 15;
                cp_async16(smb + MSB0 + row * 256 + c4 * 16,
                           Mg + (size_t)(q0 + row) * NKV + (kv0 + BK) + c4 * 4);
            }
        }
        CP_COMMIT();                 // group A_{t+1} (possibly empty; newest)
        CP_WAIT(1);                  // V(t) (group B_t) complete
        __syncthreads();

        // ---- softmax phase B (ex2 + lsum) folded into the PV loop ----
        // phaseB(nt): p = exp2(fma(s+mask, log2e, zb)); accumulate lsum; s <- p
#define PHASE_B(nt) do {                                              \
            float p0 = ex2f(fmaf(s[nt][0], LOG2E, zb));               \
            float p1 = ex2f(fmaf(s[nt][1], LOG2E, zb));               \
            float p2 = ex2f(fmaf(s[nt][2], LOG2E, zb));               \
            float p3 = ex2f(fmaf(s[nt][3], LOG2E, zb));               \
            ls0 += p0 + p1;                                           \
            ls1 += p2 + p3;                                           \
            s[nt][0] = p0; s[nt][1] = p1; s[nt][2] = p2; s[nt][3] = p3; \
        } while (0)

        PHASE_B(0);
        PHASE_B(1);

        // ---- O += P @ V (4-acc rotation); next pair's phaseB hidden in MMA shadow ----
#pragma unroll
        for (int kc = 0; kc < 4; kc++) {
            uint32_t ah[4], al[4];
            split2(s[2 * kc][0],     s[2 * kc][1],     ah[0], al[0]);
            split2(s[2 * kc][2],     s[2 * kc][3],     ah[1], al[1]);
            split2(s[2 * kc + 1][0], s[2 * kc + 1][1], ah[2], al[2]);
            split2(s[2 * kc + 1][2], s[2 * kc + 1][3], ah[3], al[3]);
            const uint32_t rv = (uint32_t)(kc * 16 + ((lane >> 3) & 1) * 8 + (lane & 7)) * KROW
                              + ((lane >> 4) << 4);
#pragma unroll
            for (int pg = 0; pg < 4; pg++) {
                const int p0 = 2 * pg, p1 = p0 + 1;
                uint32_t vh0[4], vl0[4], vh1[4], vl1[4];
                ldsm_x4_t(smb + VB0 + rv + p0 * 32,         vh0);
                ldsm_x4_t(smb + VB0 + KTILE + rv + p0 * 32, vl0);
                ldsm_x4_t(smb + VB0 + rv + p1 * 32,         vh1);
                ldsm_x4_t(smb + VB0 + KTILE + rv + p1 * 32, vl1);
                mma_bf16(o[2 * p0],     ah, vh0[0], vh0[1]);
                mma_bf16(o[2 * p0 + 1], ah, vh0[2], vh0[3]);
                mma_bf16(o[2 * p1],     ah, vh1[0], vh1[1]);
                mma_bf16(o[2 * p1 + 1], ah, vh1[2], vh1[3]);
                if (pg == 0 && kc < 3) PHASE_B(2 * kc + 2);   // hidden under MMAs
                mma_bf16(o[2 * p0],     ah, vl0[0], vl0[1]);
                mma_bf16(o[2 * p0 + 1], ah, vl0[2], vl0[3]);
                mma_bf16(o[2 * p1],     ah, vl1[0], vl1[1]);
                mma_bf16(o[2 * p1 + 1], ah, vl1[2], vl1[3]);
                if (pg == 1 && kc < 3) PHASE_B(2 * kc + 3);   // hidden under MMAs
                mma_bf16(o[2 * p0],     al, vh0[0], vh0[1]);
                mma_bf16(o[2 * p0 + 1], al, vh0[2], vh0[3]);
                mma_bf16(o[2 * p1],     al, vh1[0], vh1[1]);
                mma_bf16(o[2 * p1 + 1], al, vh1[2], vh1[3]);
            }
        }
#undef PHASE_B
    }

    // ---- epilogue ----
    ls0 += __shfl_xor_sync(0xffffffffu, ls0, 1);
    ls0 += __shfl_xor_sync(0xffffffffu, ls0, 2);
    ls1 += __shfl_xor_sync(0xffffffffu, ls1, 1);
    ls1 += __shfl_xor_sync(0xffffffffu, ls1, 2);
    const float i0 = 1.0f / ls0;
    const float i1 = 1.0f / ls1;

    float* ob = Og + ((size_t)h * NQ + q0 + wq) * HD;
#pragma unroll
    for (int nt = 0; nt < 16; nt++) {
        const int c = nt * 8 + t2 * 2;
        float2 w0 = make_float2(o[nt][0] * i0, o[nt][1] * i0);
        float2 w1 = make_float2(o[nt][2] * i1, o[nt][3] * i1);
        *(float2*)(ob + (size_t)g * HD + c)       = w0;
        *(float2*)(ob + (size_t)(g + 8) * HD + c) = w1;
    }
}

extern "C" void kernel_launch(void* const* d_in, const int* in_sizes, int n_in,
                              void* d_out, int out_size)
{
    const float* q = (const float*)d_in[0];
    const float* k = (const float*)d_in[1];
    const float* v = (const float*)d_in[2];
    const float* m = (const float*)d_in[3];
    float* o = (float*)d_out;

    // 1) convert K/V to bf16 hi/lo persistent scratch
    prep_kernel<<<2 * (KVELEMS / 4) / 256, 256>>>(k, v);

    // 2) attention: 128-thread CTAs, 2 resident per SM
    cudaFuncSetAttribute(fsdpa_mma, cudaFuncAttributeMaxDynamicSharedMemorySize, SMEM_BYTES);
    dim3 grid(NQ / BQ, NH);
    fsdpa_mma<<<grid, THREADS, SMEM_BYTES>>>(q, m, o);
}

// round 15
// speedup vs baseline: 1.7544x; 1.1722x over previous
#include <cuda_runtime.h>
#include <cuda_bf16.h>
#include <cstdint>

// ======================= constants =======================
#define NH      16
#define NQ      4096
#define NKV     8192
#define HD      128
#define PREFIX  (NKV - NQ)
#define BQ      64             // q rows per CTA (2 CTAs/SM)
#define BK      64
#define THREADS 128
#define LOG2E   1.4426950408889634f
#define SOFT_C  10.0f

#define KVELEMS (NH * NKV * HD)        // 16,777,216 per tensor

// K/V gmem + smem layout: 256B rows (128 bf16), col XOR-swizzled by (row&7)<<4.
// One 64-row tile = 16384B contiguous -> single bulk copy, ldsm conflict-free.
#define TILE_B  16384
// smem layout (bytes)
#define KB0     0                       // K hi [0,16384) + lo [16384,32768)
#define VB0     32768                   // V hi + lo [32768,65536)
#define MSB0    65536                   // mask f32 64 rows x 256B [65536,81920)
#define MBAR_K  81920
#define MBAR_V  81928
#define SMEM_BYTES 81952
// Q staging scratch (prologue only): hi in K region, lo in V region
#define QSH     0
#define QSL     32768

// ======================= persistent swizzled bf16 hi/lo copies of K and V ============
__device__ __align__(16) __nv_bfloat16 g_kh[KVELEMS];
__device__ __align__(16) __nv_bfloat16 g_kl[KVELEMS];
__device__ __align__(16) __nv_bfloat16 g_vh[KVELEMS];
__device__ __align__(16) __nv_bfloat16 g_vl[KVELEMS];

// ======================= PTX helpers (base ISA only) =======================
__device__ __forceinline__ uint32_t smem_to_u32(const void* p) {
    uint32_t a;
    asm("{ .reg .u64 t; cvta.to.shared.u64 t, %1; cvt.u32.u64 %0, t; }" : "=r"(a) : "l"(p));
    return a;
}
__device__ __forceinline__ void ldsm_x4(uint32_t addr, uint32_t* r) {
    asm volatile("ldmatrix.sync.aligned.m8n8.x4.shared.b16 {%0,%1,%2,%3}, [%4];"
                 : "=r"(r[0]), "=r"(r[1]), "=r"(r[2]), "=r"(r[3]) : "r"(addr));
}
__device__ __forceinline__ void ldsm_x4_t(uint32_t addr, uint32_t* r) {
    asm volatile("ldmatrix.sync.aligned.m8n8.x4.trans.shared.b16 {%0,%1,%2,%3}, [%4];"
                 : "=r"(r[0]), "=r"(r[1]), "=r"(r[2]), "=r"(r[3]) : "r"(addr));
}
__device__ __forceinline__ void mma_bf16(float* c, const uint32_t* a, uint32_t b0, uint32_t b1) {
    asm volatile("mma.sync.aligned.m16n8k16.row.col.f32.bf16.bf16.f32 "
                 "{%0,%1,%2,%3}, {%4,%5,%6,%7}, {%8,%9}, {%0,%1,%2,%3};"
                 : "+f"(c[0]), "+f"(c[1]), "+f"(c[2]), "+f"(c[3])
                 : "r"(a[0]), "r"(a[1]), "r"(a[2]), "r"(a[3]), "r"(b0), "r"(b1));
}
__device__ __forceinline__ uint32_t packbf(float lo, float hi) {
    uint32_t r;
    asm("cvt.rn.bf16x2.f32 %0, %1, %2;" : "=r"(r) : "f"(hi), "f"(lo));
    return r;
}
__device__ __forceinline__ float ex2f(float x) {
    float r; asm("ex2.approx.f32 %0, %1;" : "=f"(r) : "f"(x)); return r;
}
__device__ __forceinline__ void split2(float a, float b, uint32_t& hi, uint32_t& lo) {
    hi = packbf(a, b);
    float fa = __uint_as_float(hi << 16);
    float fb = __uint_as_float(hi & 0xffff0000u);
    lo = packbf(a - fa, b - fb);
}
__device__ __forceinline__ void cp_async16(uint32_t dst, const void* src) {
    asm volatile("cp.async.cg.shared.global [%0], [%1], 16;" :: "r"(dst), "l"(src) : "memory");
}
#define CP_COMMIT() asm volatile("cp.async.commit_group;" ::: "memory")
#define CP_WAIT0()  asm volatile("cp.async.wait_group 0;" ::: "memory")

// bulk DMA global->shared, completion via mbarrier complete_tx
__device__ __forceinline__ void bulk_cp(uint32_t dst, const void* src, uint32_t bytes, uint32_t mbar) {
    asm volatile("cp.async.bulk.shared::cta.global.mbarrier::complete_tx::bytes [%0], [%1], %2, [%3];"
                 :: "r"(dst), "l"(src), "r"(bytes), "r"(mbar) : "memory");
}
#define MBAR_INIT(mbar, cnt) \
    asm volatile("mbarrier.init.shared.b64 [%0], %1;" :: "r"(mbar), "r"(cnt) : "memory")
#define MBAR_EXPECT(mbar, bytes) \
    asm volatile("mbarrier.arrive.expect_tx.shared.b64 _, [%0], %1;" :: "r"(mbar), "r"(bytes) : "memory")
#define MBAR_WAIT(mbar, parity) do { \
    uint32_t _m = (mbar); uint32_t _p = (parity); uint32_t _done; \
    asm volatile("{\n\t.reg .pred p;\n\t" \
        "mbarrier.try_wait.parity.acquire.cta.shared::cta.b64 p, [%1], %2;\n\t" \
        "selp.b32 %0, 1, 0, p;\n\t}" : "=r"(_done) : "r"(_m), "r"(_p) : "memory"); \
    if (!_done) { \
        asm volatile("{\n\t.reg .pred P1;\n\t" \
            "WL_%=:\n\t" \
            "mbarrier.try_wait.parity.acquire.cta.shared::cta.b64 P1, [%0], %1, 0x989680;\n\t" \
            "@P1 bra.uni WD_%=;\n\t" \
            "bra.uni WL_%=;\n\t" \
            "WD_%=:\n\t}" :: "r"(_m), "r"(_p) : "memory"); \
    } \
} while (0)

// ======================= prep kernel: K/V f32 -> swizzled bf16 hi/lo =================
__global__ void __launch_bounds__(256)
prep_kernel(const float* __restrict__ K, const float* __restrict__ V)
{
    size_t i = (size_t)blockIdx.x * 256 + threadIdx.x;  // one 16B out-chunk per tensor
    size_t R   = i >> 4;            // row of 128 elements
    int    c16 = (int)(i & 15);     // 16B chunk within row
    size_t obase = R * 256 + (uint32_t)((c16 * 16) ^ ((int)(R & 7) << 4));
    {
        const float* s = K + R * 128 + c16 * 8;
        float4 a = *(const float4*)s, b = *(const float4*)(s + 4);
        uint32_t h[4], l[4];
        split2(a.x, a.y, h[0], l[0]); split2(a.z, a.w, h[1], l[1]);
        split2(b.x, b.y, h[2], l[2]); split2(b.z, b.w, h[3], l[3]);
        *(uint4*)((char*)g_kh + obase) = make_uint4(h[0], h[1], h[2], h[3]);
        *(uint4*)((char*)g_kl + obase) = make_uint4(l[0], l[1], l[2], l[3]);
    }
    {
        const float* s = V + R * 128 + c16 * 8;
        float4 a = *(const float4*)s, b = *(const float4*)(s + 4);
        uint32_t h[4], l[4];
        split2(a.x, a.y, h[0], l[0]); split2(a.z, a.w, h[1], l[1]);
        split2(b.x, b.y, h[2], l[2]); split2(b.z, b.w, h[3], l[3]);
        *(uint4*)((char*)g_vh + obase) = make_uint4(h[0], h[1], h[2], h[3]);
        *(uint4*)((char*)g_vl + obase) = make_uint4(l[0], l[1], l[2], l[3]);
    }
}

// ======================= main kernel =======================
__global__ void __launch_bounds__(THREADS, 2)
fsdpa_mma(const float* __restrict__ Qg, const float* __restrict__ Mg,
          float* __restrict__ Og)
{
    extern __shared__ char smem[];
    const uint32_t smb = smem_to_u32(smem);
    const int tid  = threadIdx.x;
    const int lane = tid & 31;
    const int wid  = tid >> 5;          // 0..3
    const int g    = lane >> 2;
    const int t2   = lane & 3;
    const int h    = blockIdx.y;
    const int q0   = (int)(gridDim.x - 1 - blockIdx.x) * BQ;  // longest work first
    const int wq   = wid * 16;
    const uint32_t sw = (uint32_t)(lane & 7) << 4;   // ldsm row swizzle

    const size_t rowbase = (size_t)h * NKV;          // row index base (256B rows)
    const int ntiles = (PREFIX + q0 + BQ) / BK;

    if (tid == 0) { MBAR_INIT(smb + MBAR_K, 1); MBAR_INIT(smb + MBAR_V, 1); }
    __syncthreads();

    // ---- stage Q (scale folded) into scratch (K/V regions, swizzled rows) ----
    {
        const float scale = 0.08838834764831845f;   // 1/sqrt(128)
        const float* qb = Qg + ((size_t)h * NQ + q0) * HD;
#pragma unroll
        for (int i = 0; i < 16; i++) {
            int gi  = tid + i * THREADS;
            int row = gi >> 5, c4 = (gi & 31) << 2;
            float4 v = *(const float4*)(qb + (size_t)row * HD + c4);
            v.x *= scale; v.y *= scale; v.z *= scale; v.w *= scale;
            uint32_t h01, l01, h23, l23;
            split2(v.x, v.y, h01, l01);
            split2(v.z, v.w, h23, l23);
            int off = row * 256 + ((c4 * 2) ^ ((row & 7) << 4));
            *(uint2*)(smem + QSH + off) = make_uint2(h01, h23);
            *(uint2*)(smem + QSL + off) = make_uint2(l01, l23);
        }
    }
    __syncthreads();

    uint32_t qh[8][4], ql[8][4];
    {
        const int mi = lane >> 3;
        const uint32_t qrow = (uint32_t)(wq + (lane & 7) + ((mi & 1) << 3)) * 256;
        const uint32_t qcol = (uint32_t)((mi >> 1) << 4);
#pragma unroll
        for (int kc = 0; kc < 8; kc++) {
            uint32_t off = qrow + ((qcol + kc * 32) ^ sw);
            ldsm_x4(smb + QSH + off, qh[kc]);
            ldsm_x4(smb + QSL + off, ql[kc]);
        }
    }
    __syncthreads();   // Q in regs; K/V regions free for DMA

    // ---- issue K(0) bulk + mask(0) cp.async ----
    if (tid == 0) {
        MBAR_EXPECT(smb + MBAR_K, 2 * TILE_B);
        bulk_cp(smb + KB0,          (const char*)g_kh + rowbase * 256, TILE_B, smb + MBAR_K);
        bulk_cp(smb + KB0 + TILE_B, (const char*)g_kl + rowbase * 256, TILE_B, smb + MBAR_K);
    }
#pragma unroll
    for (int i = 0; i < 8; i++) {
        int gi = tid + i * THREADS;
        int row = gi >> 4, c4 = gi & 15;
        cp_async16(smb + MSB0 + row * 256 + c4 * 16, Mg + (size_t)(q0 + row) * NKV + c4 * 4);
    }
    CP_COMMIT();

    float o[16][4];
#pragma unroll
    for (int i = 0; i < 16; i++)
#pragma unroll
        for (int j = 0; j < 4; j++) o[i][j] = 0.0f;
    float ls0 = 0.0f, ls1 = 0.0f;
    int ph_k = 0, ph_v = 0;

    const float* msf = (const float*)(smem + MSB0);
    const float zb = -SOFT_C * LOG2E;

    for (int t = 0; t < ntiles; t++) {
        const int kv0 = t * BK;

        // loop top: drain OWN mask copies BEFORE the barrier so the barrier
        // publishes everyone's mask(t) writes (fixes R14 visibility race),
        // and orders PV(t-1) V-reads before the V(t) bulk issue.
        CP_WAIT0();
        __syncthreads();
        if (tid == 0) {
            MBAR_EXPECT(smb + MBAR_V, 2 * TILE_B);
            bulk_cp(smb + VB0,          (const char*)g_vh + (rowbase + kv0) * 256, TILE_B, smb + MBAR_V);
            bulk_cp(smb + VB0 + TILE_B, (const char*)g_vl + (rowbase + kv0) * 256, TILE_B, smb + MBAR_V);
        }
        MBAR_WAIT(smb + MBAR_K, ph_k);      // K(t) arrived (acquire, all threads)
        ph_k ^= 1;

        // ---- S = Q @ K^T: 4-accumulator rotation ----
        float s[8][4];
#pragma unroll
        for (int i = 0; i < 8; i++)
#pragma unroll
            for (int j = 0; j < 4; j++) s[i][j] = 0.0f;

#pragma unroll
        for (int kcp = 0; kcp < 4; kcp++) {
            const int kc = 2 * kcp;
#pragma unroll
            for (int half = 0; half < 2; half++) {
                const int ntb = 4 * half;
                uint32_t fh[4][4], fl[4][4];
#pragma unroll
                for (int j = 0; j < 4; j++) {
                    const uint32_t row = (uint32_t)((ntb + j) * 8 + (lane & 7)) * 256;
                    const uint32_t col = (uint32_t)(((lane >> 3) << 4) + kcp * 64);
                    const uint32_t off = row + (col ^ sw);
                    ldsm_x4(smb + KB0 + off,          fh[j]);
                    ldsm_x4(smb + KB0 + TILE_B + off, fl[j]);
                }
#pragma unroll
                for (int j = 0; j < 4; j++) mma_bf16(s[ntb + j], qh[kc],     fh[j][0], fh[j][1]);
#pragma unroll
                for (int j = 0; j < 4; j++) mma_bf16(s[ntb + j], qh[kc],     fl[j][0], fl[j][1]);
#pragma unroll
                for (int j = 0; j < 4; j++) mma_bf16(s[ntb + j], ql[kc],     fh[j][0], fh[j][1]);
#pragma unroll
                for (int j = 0; j < 4; j++) mma_bf16(s[ntb + j], qh[kc + 1], fh[j][2], fh[j][3]);
#pragma unroll
                for (int j = 0; j < 4; j++) mma_bf16(s[ntb + j], qh[kc + 1], fl[j][2], fl[j][3]);
#pragma unroll
                for (int j = 0; j < 4; j++) mma_bf16(s[ntb + j], ql[kc + 1], fh[j][2], fh[j][3]);
            }
        }

        // ---- softmax phase A: s += mask, causal sentinel ----
        {
            const int  lim0 = PREFIX + q0 + wq + g - kv0;
            const int  lim1 = lim0 + 8;
            const bool dg   = (t >= ntiles - 1);
            const float* mrow0 = msf + (wq + g) * 64;
            const float* mrow1 = mrow0 + 8 * 64;
#pragma unroll
            for (int nt = 0; nt < 8; nt++) {
                const int c = nt * 8 + t2 * 2;
                float2 m0 = *(const float2*)(mrow0 + c);
                float2 m1 = *(const float2*)(mrow1 + c);
                s[nt][0] += m0.x;
                s[nt][1] += m0.y;
                s[nt][2] += m1.x;
                s[nt][3] += m1.y;
                if (dg) {
                    if (c     > lim0) s[nt][0] = -200.0f;
                    if (c + 1 > lim0) s[nt][1] = -200.0f;
                    if (c     > lim1) s[nt][2] = -200.0f;
                    if (c + 1 > lim1) s[nt][3] = -200.0f;
                }
            }
        }

        // mid: K(t)/mask(t) readers done -> issue K(t+1) bulk + mask(t+1)
        __syncthreads();
        if (t + 1 < ntiles) {
            if (tid == 0) {
                MBAR_EXPECT(smb + MBAR_K, 2 * TILE_B);
                bulk_cp(smb + KB0,          (const char*)g_kh + (rowbase + kv0 + BK) * 256, TILE_B, smb + MBAR_K);
                bulk_cp(smb + KB0 + TILE_B, (const char*)g_kl + (rowbase + kv0 + BK) * 256, TILE_B, smb + MBAR_K);
            }
#pragma unroll
            for (int i = 0; i < 8; i++) {
                int gi = tid + i * THREADS;
                int row = gi >> 4, c4 = gi & 15;
                cp_async16(smb + MSB0 + row * 256 + c4 * 16,
                           Mg + (size_t)(q0 + row) * NKV + (kv0 + BK) + c4 * 4);
            }
        }
        CP_COMMIT();
        MBAR_WAIT(smb + MBAR_V, ph_v);      // V(t) arrived (acquire)
        ph_v ^= 1;

        // ---- softmax phase B folded into PV ----
#define PHASE_B(nt) do {                                              \
            float p0 = ex2f(fmaf(s[nt][0], LOG2E, zb));               \
            float p1 = ex2f(fmaf(s[nt][1], LOG2E, zb));               \
            float p2 = ex2f(fmaf(s[nt][2], LOG2E, zb));               \
            float p3 = ex2f(fmaf(s[nt][3], LOG2E, zb));               \
            ls0 += p0 + p1;                                           \
            ls1 += p2 + p3;                                           \
            s[nt][0] = p0; s[nt][1] = p1; s[nt][2] = p2; s[nt][3] = p3; \
        } while (0)

        PHASE_B(0);
        PHASE_B(1);

        // ---- O += P @ V (4-acc rotation) ----
#pragma unroll
        for (int kc = 0; kc < 4; kc++) {
            uint32_t ah[4], al[4];
            split2(s[2 * kc][0],     s[2 * kc][1],     ah[0], al[0]);
            split2(s[2 * kc][2],     s[2 * kc][3],     ah[1], al[1]);
            split2(s[2 * kc + 1][0], s[2 * kc + 1][1], ah[2], al[2]);
            split2(s[2 * kc + 1][2], s[2 * kc + 1][3], ah[3], al[3]);
            const uint32_t vrow = (uint32_t)(kc * 16 + ((lane >> 3) & 1) * 8 + (lane & 7)) * 256;
            const uint32_t vcb  = (uint32_t)((lane >> 4) << 4);
#pragma unroll
            for (int pg = 0; pg < 4; pg++) {
                const int p0 = 2 * pg, p1 = p0 + 1;
                const uint32_t off0 = vrow + ((vcb + p0 * 32) ^ sw);
                const uint32_t off1 = vrow + ((vcb + p1 * 32) ^ sw);
                uint32_t vh0[4], vl0[4], vh1[4], vl1[4];
                ldsm_x4_t(smb + VB0 + off0,          vh0);
                ldsm_x4_t(smb + VB0 + TILE_B + off0, vl0);
                ldsm_x4_t(smb + VB0 + off1,          vh1);
                ldsm_x4_t(smb + VB0 + TILE_B + off1, vl1);
                mma_bf16(o[2 * p0],     ah, vh0[0], vh0[1]);
                mma_bf16(o[2 * p0 + 1], ah, vh0[2], vh0[3]);
                mma_bf16(o[2 * p1],     ah, vh1[0], vh1[1]);
                mma_bf16(o[2 * p1 + 1], ah, vh1[2], vh1[3]);
                if (pg == 0 && kc < 3) PHASE_B(2 * kc + 2);
                mma_bf16(o[2 * p0],     ah, vl0[0], vl0[1]);
                mma_bf16(o[2 * p0 + 1], ah, vl0[2], vl0[3]);
                mma_bf16(o[2 * p1],     ah, vl1[0], vl1[1]);
                mma_bf16(o[2 * p1 + 1], ah, vl1[2], vl1[3]);
                if (pg == 1 && kc < 3) PHASE_B(2 * kc + 3);
                mma_bf16(o[2 * p0],     al, vh0[0], vh0[1]);
                mma_bf16(o[2 * p0 + 1], al, vh0[2], vh0[3]);
                mma_bf16(o[2 * p1],     al, vh1[0], vh1[1]);
                mma_bf16(o[2 * p1 + 1], al, vh1[2], vh1[3]);
            }
        }
#undef PHASE_B
    }

    // ---- epilogue ----
    ls0 += __shfl_xor_sync(0xffffffffu, ls0, 1);
    ls0 += __shfl_xor_sync(0xffffffffu, ls0, 2);
    ls1 += __shfl_xor_sync(0xffffffffu, ls1, 1);
    ls1 += __shfl_xor_sync(0xffffffffu, ls1, 2);
    const float i0 = 1.0f / ls0;
    const float i1 = 1.0f / ls1;

    float* ob = Og + ((size_t)h * NQ + q0 + wq) * HD;
#pragma unroll
    for (int nt = 0; nt < 16; nt++) {
        const int c = nt * 8 + t2 * 2;
        float2 w0 = make_float2(o[nt][0] * i0, o[nt][1] * i0);
        float2 w1 = make_float2(o[nt][2] * i1, o[nt][3] * i1);
        *(float2*)(ob + (size_t)g * HD + c)       = w0;
        *(float2*)(ob + (size_t)(g + 8) * HD + c) = w1;
    }
}

extern "C" void kernel_launch(void* const* d_in, const int* in_sizes, int n_in,
                              void* d_out, int out_size)
{
    const float* q = (const float*)d_in[0];
    const float* k = (const float*)d_in[1];
    const float* v = (const float*)d_in[2];
    const float* m = (const float*)d_in[3];
    float* o = (float*)d_out;

    // 1) convert K/V to swizzled bf16 hi/lo persistent scratch
    prep_kernel<<<(KVELEMS / 8) / 256, 256>>>(k, v);

    // 2) attention: 128-thread CTAs, 2 resident per SM
    cudaFuncSetAttribute(fsdpa_mma, cudaFuncAttributeMaxDynamicSharedMemorySize, SMEM_BYTES);
    dim3 grid(NQ / BQ, NH);
    fsdpa_mma<<<grid, THREADS, SMEM_BYTES>>>(q, m, o);
}

// round 16
// speedup vs baseline: 1.7956x; 1.0235x over previous
#include <cuda_runtime.h>
#include <cuda_bf16.h>
#include <cstdint>

// ======================= constants =======================
#define NH      16
#define NQ      4096
#define NKV     8192
#define HD      128
#define PREFIX  (NKV - NQ)
#define BQ      64             // q rows per CTA (2 CTAs/SM)
#define BK      64
#define THREADS 128
#define LOG2E   1.4426950408889634f
#define SOFT_C  10.0f

#define KVELEMS (NH * NKV * HD)        // 16,777,216 per tensor

// K/V gmem + smem layout: 256B rows (128 bf16), col XOR-swizzled by (row&7)<<4.
// One 64-row tile = 16384B contiguous -> single bulk copy, ldsm conflict-free.
#define TILE_B  16384
// smem layout (bytes)
#define KB(b)   ((b) * 32768)           // K hi [0,16K) + lo [16K,32K), double buffered
#define VB0     65536                   // V hi [65536,81920) + lo [81920,98304)
#define MBAR_K  98304
#define MBAR_V  98312
#define SMEM_BYTES 98336
// Q staging scratch (prologue only): hi in KB(0), lo in KB(1)
#define QSH     0
#define QSL     32768

// ======================= persistent swizzled bf16 hi/lo copies of K and V ============
__device__ __align__(16) __nv_bfloat16 g_kh[KVELEMS];
__device__ __align__(16) __nv_bfloat16 g_kl[KVELEMS];
__device__ __align__(16) __nv_bfloat16 g_vh[KVELEMS];
__device__ __align__(16) __nv_bfloat16 g_vl[KVELEMS];

// ======================= PTX helpers (base ISA only) =======================
__device__ __forceinline__ uint32_t smem_to_u32(const void* p) {
    uint32_t a;
    asm("{ .reg .u64 t; cvta.to.shared.u64 t, %1; cvt.u32.u64 %0, t; }" : "=r"(a) : "l"(p));
    return a;
}
__device__ __forceinline__ void ldsm_x4(uint32_t addr, uint32_t* r) {
    asm volatile("ldmatrix.sync.aligned.m8n8.x4.shared.b16 {%0,%1,%2,%3}, [%4];"
                 : "=r"(r[0]), "=r"(r[1]), "=r"(r[2]), "=r"(r[3]) : "r"(addr));
}
__device__ __forceinline__ void ldsm_x4_t(uint32_t addr, uint32_t* r) {
    asm volatile("ldmatrix.sync.aligned.m8n8.x4.trans.shared.b16 {%0,%1,%2,%3}, [%4];"
                 : "=r"(r[0]), "=r"(r[1]), "=r"(r[2]), "=r"(r[3]) : "r"(addr));
}
__device__ __forceinline__ void mma_bf16(float* c, const uint32_t* a, uint32_t b0, uint32_t b1) {
    asm volatile("mma.sync.aligned.m16n8k16.row.col.f32.bf16.bf16.f32 "
                 "{%0,%1,%2,%3}, {%4,%5,%6,%7}, {%8,%9}, {%0,%1,%2,%3};"
                 : "+f"(c[0]), "+f"(c[1]), "+f"(c[2]), "+f"(c[3])
                 : "r"(a[0]), "r"(a[1]), "r"(a[2]), "r"(a[3]), "r"(b0), "r"(b1));
}
__device__ __forceinline__ uint32_t packbf(float lo, float hi) {
    uint32_t r;
    asm("cvt.rn.bf16x2.f32 %0, %1, %2;" : "=r"(r) : "f"(hi), "f"(lo));
    return r;
}
__device__ __forceinline__ float ex2f(float x) {
    float r; asm("ex2.approx.f32 %0, %1;" : "=f"(r) : "f"(x)); return r;
}
__device__ __forceinline__ void split2(float a, float b, uint32_t& hi, uint32_t& lo) {
    hi = packbf(a, b);
    float fa = __uint_as_float(hi << 16);
    float fb = __uint_as_float(hi & 0xffff0000u);
    lo = packbf(a - fa, b - fb);
}

// bulk DMA global->shared, completion via mbarrier complete_tx
__device__ __forceinline__ void bulk_cp(uint32_t dst, const void* src, uint32_t bytes, uint32_t mbar) {
    asm volatile("cp.async.bulk.shared::cta.global.mbarrier::complete_tx::bytes [%0], [%1], %2, [%3];"
                 :: "r"(dst), "l"(src), "r"(bytes), "r"(mbar) : "memory");
}
#define MBAR_INIT(mbar, cnt) \
    asm volatile("mbarrier.init.shared.b64 [%0], %1;" :: "r"(mbar), "r"(cnt) : "memory")
#define MBAR_EXPECT(mbar, bytes) \
    asm volatile("mbarrier.arrive.expect_tx.shared.b64 _, [%0], %1;" :: "r"(mbar), "r"(bytes) : "memory")
#define MBAR_WAIT(mbar, parity) do { \
    uint32_t _m = (mbar); uint32_t _p = (parity); uint32_t _done; \
    asm volatile("{\n\t.reg .pred p;\n\t" \
        "mbarrier.try_wait.parity.acquire.cta.shared::cta.b64 p, [%1], %2;\n\t" \
        "selp.b32 %0, 1, 0, p;\n\t}" : "=r"(_done) : "r"(_m), "r"(_p) : "memory"); \
    if (!_done) { \
        asm volatile("{\n\t.reg .pred P1;\n\t" \
            "WL_%=:\n\t" \
            "mbarrier.try_wait.parity.acquire.cta.shared::cta.b64 P1, [%0], %1, 0x989680;\n\t" \
            "@P1 bra.uni WD_%=;\n\t" \
            "bra.uni WL_%=;\n\t" \
            "WD_%=:\n\t}" :: "r"(_m), "r"(_p) : "memory"); \
    } \
} while (0)

// ======================= prep kernel: K/V f32 -> swizzled bf16 hi/lo =================
__global__ void __launch_bounds__(256)
prep_kernel(const float* __restrict__ K, const float* __restrict__ V)
{
    size_t i = (size_t)blockIdx.x * 256 + threadIdx.x;  // one 16B out-chunk per tensor
    size_t R   = i >> 4;            // row of 128 elements
    int    c16 = (int)(i & 15);     // 16B chunk within row
    size_t obase = R * 256 + (uint32_t)((c16 * 16) ^ ((int)(R & 7) << 4));
    {
        const float* s = K + R * 128 + c16 * 8;
        float4 a = *(const float4*)s, b = *(const float4*)(s + 4);
        uint32_t h[4], l[4];
        split2(a.x, a.y, h[0], l[0]); split2(a.z, a.w, h[1], l[1]);
        split2(b.x, b.y, h[2], l[2]); split2(b.z, b.w, h[3], l[3]);
        *(uint4*)((char*)g_kh + obase) = make_uint4(h[0], h[1], h[2], h[3]);
        *(uint4*)((char*)g_kl + obase) = make_uint4(l[0], l[1], l[2], l[3]);
    }
    {
        const float* s = V + R * 128 + c16 * 8;
        float4 a = *(const float4*)s, b = *(const float4*)(s + 4);
        uint32_t h[4], l[4];
        split2(a.x, a.y, h[0], l[0]); split2(a.z, a.w, h[1], l[1]);
        split2(b.x, b.y, h[2], l[2]); split2(b.z, b.w, h[3], l[3]);
        *(uint4*)((char*)g_vh + obase) = make_uint4(h[0], h[1], h[2], h[3]);
        *(uint4*)((char*)g_vl + obase) = make_uint4(l[0], l[1], l[2], l[3]);
    }
}

// ======================= main kernel =======================
__global__ void __launch_bounds__(THREADS, 2)
fsdpa_mma(const float* __restrict__ Qg, const float* __restrict__ Mg,
          float* __restrict__ Og)
{
    extern __shared__ char smem[];
    const uint32_t smb = smem_to_u32(smem);
    const int tid  = threadIdx.x;
    const int lane = tid & 31;
    const int g    = lane >> 2;
    const int t2   = lane & 3;
    const int wid  = tid >> 5;          // 0..3
    const int h    = blockIdx.y;
    const int q0   = (int)(gridDim.x - 1 - blockIdx.x) * BQ;  // longest work first
    const int wq   = wid * 16;
    const uint32_t sw = (uint32_t)(lane & 7) << 4;   // ldsm row swizzle

    const size_t rowbase = (size_t)h * NKV;          // row index base (256B rows)
    const int ntiles = (PREFIX + q0 + BQ) / BK;

    if (tid == 0) { MBAR_INIT(smb + MBAR_K, 1); MBAR_INIT(smb + MBAR_V, 1); }
    __syncthreads();

    // ---- stage Q (scale folded) into scratch (K regions, swizzled rows) ----
    {
        const float scale = 0.08838834764831845f;   // 1/sqrt(128)
        const float* qb = Qg + ((size_t)h * NQ + q0) * HD;
#pragma unroll
        for (int i = 0; i < 16; i++) {
            int gi  = tid + i * THREADS;
            int row = gi >> 5, c4 = (gi & 31) << 2;
            float4 v = *(const float4*)(qb + (size_t)row * HD + c4);
            v.x *= scale; v.y *= scale; v.z *= scale; v.w *= scale;
            uint32_t h01, l01, h23, l23;
            split2(v.x, v.y, h01, l01);
            split2(v.z, v.w, h23, l23);
            int off = row * 256 + ((c4 * 2) ^ ((row & 7) << 4));
            *(uint2*)(smem + QSH + off) = make_uint2(h01, h23);
            *(uint2*)(smem + QSL + off) = make_uint2(l01, l23);
        }
    }
    __syncthreads();

    uint32_t qh[8][4], ql[8][4];
    {
        const int mi = lane >> 3;
        const uint32_t qrow = (uint32_t)(wq + (lane & 7) + ((mi & 1) << 3)) * 256;
        const uint32_t qcol = (uint32_t)((mi >> 1) << 4);
#pragma unroll
        for (int kc = 0; kc < 8; kc++) {
            uint32_t off = qrow + ((qcol + kc * 32) ^ sw);
            ldsm_x4(smb + QSH + off, qh[kc]);
            ldsm_x4(smb + QSL + off, ql[kc]);
        }
    }
    __syncthreads();   // Q in regs; K regions free for DMA

    // ---- issue K(0) bulk into KB(0) ----
    if (tid == 0) {
        MBAR_EXPECT(smb + MBAR_K, 2 * TILE_B);
        bulk_cp(smb + KB(0),          (const char*)g_kh + rowbase * 256, TILE_B, smb + MBAR_K);
        bulk_cp(smb + KB(0) + TILE_B, (const char*)g_kl + rowbase * 256, TILE_B, smb + MBAR_K);
    }

    float o[16][4];
#pragma unroll
    for (int i = 0; i < 16; i++)
#pragma unroll
        for (int j = 0; j < 4; j++) o[i][j] = 0.0f;
    float ls0 = 0.0f, ls1 = 0.0f;
    int ph_k = 0, ph_v = 0;

    const float zb = -SOFT_C * LOG2E;
    const float* mrowg0 = Mg + (size_t)(q0 + wq + g) * NKV;   // mask row (g)
    const float* mrowg1 = mrowg0 + 8 * NKV;                   // mask row (g+8)

    for (int t = 0; t < ntiles; t++) {
        const int kv0 = t * BK;
        const int buf = t & 1;
        const int kbh = KB(buf), kbl = kbh + TILE_B;

        // loop top: single CTA barrier.
        // Publishes: PV(t-1) done with V region; QK(t-1) done with KB(buf^1).
        __syncthreads();
        if (tid == 0) {
            MBAR_EXPECT(smb + MBAR_V, 2 * TILE_B);   // V phase (t-1) completed mid-(t-1)
            bulk_cp(smb + VB0,          (const char*)g_vh + (rowbase + kv0) * 256, TILE_B, smb + MBAR_V);
            bulk_cp(smb + VB0 + TILE_B, (const char*)g_vl + (rowbase + kv0) * 256, TILE_B, smb + MBAR_V);
        }
        MBAR_WAIT(smb + MBAR_K, ph_k);      // K(t) arrived (acquire, all threads)
        ph_k ^= 1;
        // K phase t completed -> safe to open phase t+1 and prefetch into buf^1
        if (t + 1 < ntiles && tid == 0) {
            MBAR_EXPECT(smb + MBAR_K, 2 * TILE_B);
            bulk_cp(smb + KB(buf ^ 1),          (const char*)g_kh + (rowbase + kv0 + BK) * 256, TILE_B, smb + MBAR_K);
            bulk_cp(smb + KB(buf ^ 1) + TILE_B, (const char*)g_kl + (rowbase + kv0 + BK) * 256, TILE_B, smb + MBAR_K);
        }

        // ---- S = Q @ K^T: 4-accumulator rotation ----
        float s[8][4];
#pragma unroll
        for (int i = 0; i < 8; i++)
#pragma unroll
            for (int j = 0; j < 4; j++) s[i][j] = 0.0f;

#pragma unroll
        for (int kcp = 0; kcp < 4; kcp++) {
            const int kc = 2 * kcp;
#pragma unroll
            for (int half = 0; half < 2; half++) {
                const int ntb = 4 * half;
                uint32_t fh[4][4], fl[4][4];
#pragma unroll
                for (int j = 0; j < 4; j++) {
                    const uint32_t row = (uint32_t)((ntb + j) * 8 + (lane & 7)) * 256;
                    const uint32_t col = (uint32_t)(((lane >> 3) << 4) + kcp * 64);
                    const uint32_t off = row + (col ^ sw);
                    ldsm_x4(smb + kbh + off, fh[j]);
                    ldsm_x4(smb + kbl + off, fl[j]);
                }
#pragma unroll
                for (int j = 0; j < 4; j++) mma_bf16(s[ntb + j], qh[kc],     fh[j][0], fh[j][1]);
#pragma unroll
                for (int j = 0; j < 4; j++) mma_bf16(s[ntb + j], qh[kc],     fl[j][0], fl[j][1]);
#pragma unroll
                for (int j = 0; j < 4; j++) mma_bf16(s[ntb + j], ql[kc],     fh[j][0], fh[j][1]);
#pragma unroll
                for (int j = 0; j < 4; j++) mma_bf16(s[ntb + j], qh[kc + 1], fh[j][2], fh[j][3]);
#pragma unroll
                for (int j = 0; j < 4; j++) mma_bf16(s[ntb + j], qh[kc + 1], fl[j][2], fl[j][3]);
#pragma unroll
                for (int j = 0; j < 4; j++) mma_bf16(s[ntb + j], ql[kc + 1], fh[j][2], fh[j][3]);
            }
        }

        // ---- softmax phase A: s += mask (direct gmem LDG), causal sentinel ----
        {
            const int  lim0 = PREFIX + q0 + wq + g - kv0;
            const int  lim1 = lim0 + 8;
            const bool dg   = (t >= ntiles - 1);
            const float* m0p = mrowg0 + kv0;
            const float* m1p = mrowg1 + kv0;
#pragma unroll
            for (int nt = 0; nt < 8; nt++) {
                const int c = nt * 8 + t2 * 2;
                float2 m0 = *(const float2*)(m0p + c);
                float2 m1 = *(const float2*)(m1p + c);
                s[nt][0] += m0.x;
                s[nt][1] += m0.y;
                s[nt][2] += m1.x;
                s[nt][3] += m1.y;
                if (dg) {
                    if (c     > lim0) s[nt][0] = -200.0f;
                    if (c + 1 > lim0) s[nt][1] = -200.0f;
                    if (c     > lim1) s[nt][2] = -200.0f;
                    if (c + 1 > lim1) s[nt][3] = -200.0f;
                }
            }
        }

        MBAR_WAIT(smb + MBAR_V, ph_v);      // V(t) arrived (acquire)
        ph_v ^= 1;

        // ---- softmax phase B folded into PV ----
#define PHASE_B(nt) do {                                              \
            float p0 = ex2f(fmaf(s[nt][0], LOG2E, zb));               \
            float p1 = ex2f(fmaf(s[nt][1], LOG2E, zb));               \
            float p2 = ex2f(fmaf(s[nt][2], LOG2E, zb));               \
            float p3 = ex2f(fmaf(s[nt][3], LOG2E, zb));               \
            ls0 += p0 + p1;                                           \
            ls1 += p2 + p3;                                           \
            s[nt][0] = p0; s[nt][1] = p1; s[nt][2] = p2; s[nt][3] = p3; \
        } while (0)

        PHASE_B(0);
        PHASE_B(1);

        // ---- O += P @ V (4-acc rotation) ----
#pragma unroll
        for (int kc = 0; kc < 4; kc++) {
            uint32_t ah[4], al[4];
            split2(s[2 * kc][0],     s[2 * kc][1],     ah[0], al[0]);
            split2(s[2 * kc][2],     s[2 * kc][3],     ah[1], al[1]);
            split2(s[2 * kc + 1][0], s[2 * kc + 1][1], ah[2], al[2]);
            split2(s[2 * kc + 1][2], s[2 * kc + 1][3], ah[3], al[3]);
            const uint32_t vrow = (uint32_t)(kc * 16 + ((lane >> 3) & 1) * 8 + (lane & 7)) * 256;
            const uint32_t vcb  = (uint32_t)((lane >> 4) << 4);
#pragma unroll
            for (int pg = 0; pg < 4; pg++) {
                const int p0 = 2 * pg, p1 = p0 + 1;
                const uint32_t off0 = vrow + ((vcb + p0 * 32) ^ sw);
                const uint32_t off1 = vrow + ((vcb + p1 * 32) ^ sw);
                uint32_t vh0[4], vl0[4], vh1[4], vl1[4];
                ldsm_x4_t(smb + VB0 + off0,          vh0);
                ldsm_x4_t(smb + VB0 + TILE_B + off0, vl0);
                ldsm_x4_t(smb + VB0 + off1,          vh1);
                ldsm_x4_t(smb + VB0 + TILE_B + off1, vl1);
                mma_bf16(o[2 * p0],     ah, vh0[0], vh0[1]);
                mma_bf16(o[2 * p0 + 1], ah, vh0[2], vh0[3]);
                mma_bf16(o[2 * p1],     ah, vh1[0], vh1[1]);
                mma_bf16(o[2 * p1 + 1], ah, vh1[2], vh1[3]);
                if (pg == 0 && kc < 3) PHASE_B(2 * kc + 2);
                mma_bf16(o[2 * p0],     ah, vl0[0], vl0[1]);
                mma_bf16(o[2 * p0 + 1], ah, vl0[2], vl0[3]);
                mma_bf16(o[2 * p1],     ah, vl1[0], vl1[1]);
                mma_bf16(o[2 * p1 + 1], ah, vl1[2], vl1[3]);
                if (pg == 1 && kc < 3) PHASE_B(2 * kc + 3);
                mma_bf16(o[2 * p0],     al, vh0[0], vh0[1]);
                mma_bf16(o[2 * p0 + 1], al, vh0[2], vh0[3]);
                mma_bf16(o[2 * p1],     al, vh1[0], vh1[1]);
                mma_bf16(o[2 * p1 + 1], al, vh1[2], vh1[3]);
            }
        }
#undef PHASE_B
    }

    // ---- epilogue ----
    ls0 += __shfl_xor_sync(0xffffffffu, ls0, 1);
    ls0 += __shfl_xor_sync(0xffffffffu, ls0, 2);
    ls1 += __shfl_xor_sync(0xffffffffu, ls1, 1);
    ls1 += __shfl_xor_sync(0xffffffffu, ls1, 2);
    const float i0 = 1.0f / ls0;
    const float i1 = 1.0f / ls1;

    float* ob = Og + ((size_t)h * NQ + q0 + wq) * HD;
#pragma unroll
    for (int nt = 0; nt < 16; nt++) {
        const int c = nt * 8 + t2 * 2;
        float2 w0 = make_float2(o[nt][0] * i0, o[nt][1] * i0);
        float2 w1 = make_float2(o[nt][2] * i1, o[nt][3] * i1);
        *(float2*)(ob + (size_t)g * HD + c)       = w0;
        *(float2*)(ob + (size_t)(g + 8) * HD + c) = w1;
    }
}

extern "C" void kernel_launch(void* const* d_in, const int* in_sizes, int n_in,
                              void* d_out, int out_size)
{
    const float* q = (const float*)d_in[0];
    const float* k = (const float*)d_in[1];
    const float* v = (const float*)d_in[2];
    const float* m = (const float*)d_in[3];
    float* o = (float*)d_out;

    // 1) convert K/V to swizzled bf16 hi/lo persistent scratch
    prep_kernel<<<(KVELEMS / 8) / 256, 256>>>(k, v);

    // 2) attention: 128-thread CTAs, 2 resident per SM
    cudaFuncSetAttribute(fsdpa_mma, cudaFuncAttributeMaxDynamicSharedMemorySize, SMEM_BYTES);
    dim3 grid(NQ / BQ, NH);
    fsdpa_mma<<<grid, THREADS, SMEM_BYTES>>>(q, m, o);
}